// round 1
// baseline (speedup 1.0000x reference)
#include <cuda_runtime.h>
#include <cstdint>

// Problem constants
#define BATCH 8
#define CFULL 512
#define CI    256
#define LQ    4096
#define LK    2048   // L/2

#define BM 128
#define BN 128
#define BK 16
#define PAD 4

// ---------------- scratch (device globals; no allocations allowed) ----------
__device__ float g_theta[BATCH * CI * LQ];            // [B][Ci][L]
__device__ float g_phi  [BATCH * CI * LK];            // [B][Ci][L/2]
__device__ float g_gbuf [BATCH * CI * LK];            // [B][Ci][L/2]
__device__ float g_f    [(size_t)BATCH * LQ * LK];    // [B][L][L/2]  256MB
__device__ float g_y    [BATCH * CI * LQ];            // [B][Ci][L]
__device__ float g_z    [BATCH * CFULL * LQ];         // [B][C][L]
__device__ float g_mean [CFULL];
__device__ float g_var  [CFULL];

// ---------------- generic tiled SGEMM ---------------------------------------
// C[m,n] = sum_k A(m,k) * B(k,n)  (+bias[m]) (optional maxpool2 along n)
// TA=0: A is [M,K] row-major (k contiguous).  TA=1: A is [K,M] row-major (m contiguous).
// TB=0: B is [K,N] row-major (n contiguous).  TB=1: B is [N,K] row-major (k contiguous).
// Assumes M%128==0, N%128==0, K%16==0.
template<int TA, int TB, int POOL, int BIAS>
__global__ __launch_bounds__(256, 2)
void gemm_kernel(const float* __restrict__ A, const float* __restrict__ B,
                 const float* __restrict__ bias, float* __restrict__ C,
                 int M, int N, int K, int ldc,
                 long sAb, long sBb, long sCb)
{
    __shared__ float As[BK][BM + PAD];
    __shared__ float Bs[BK][BN + PAD];

    const int tid = threadIdx.x;
    const int bm = blockIdx.y * BM;
    const int bn = blockIdx.x * BN;
    A += (long)blockIdx.z * sAb;
    B += (long)blockIdx.z * sBb;
    C += (long)blockIdx.z * sCb;

    const int tx = tid & 15;
    const int ty = tid >> 4;
    const int m0 = ty * 8;
    const int n0 = tx * 8;

    float acc[8][8];
    #pragma unroll
    for (int i = 0; i < 8; i++)
        #pragma unroll
        for (int j = 0; j < 8; j++)
            acc[i][j] = 0.f;

    for (int k0 = 0; k0 < K; k0 += BK) {
        // ---- load A tile ----
        #pragma unroll
        for (int it = 0; it < (BM * BK) / 256; it++) {
            int idx = tid + it * 256;
            if (TA) {
                int m = idx & (BM - 1), k = idx >> 7;          // m contiguous in gmem
                As[k][m] = __ldg(&A[(long)(k0 + k) * M + bm + m]);
            } else {
                int k = idx & (BK - 1), m = idx >> 4;          // k contiguous in gmem
                As[k][m] = __ldg(&A[(long)(bm + m) * K + k0 + k]);
            }
        }
        // ---- load B tile ----
        #pragma unroll
        for (int it = 0; it < (BN * BK) / 256; it++) {
            int idx = tid + it * 256;
            if (TB) {
                int k = idx & (BK - 1), n = idx >> 4;          // k contiguous in gmem
                Bs[k][n] = __ldg(&B[(long)(bn + n) * K + k0 + k]);
            } else {
                int n = idx & (BN - 1), k = idx >> 7;          // n contiguous in gmem
                Bs[k][n] = __ldg(&B[(long)(k0 + k) * N + bn + n]);
            }
        }
        __syncthreads();

        #pragma unroll
        for (int k = 0; k < BK; k++) {
            float a[8], b[8];
            *(float4*)&a[0] = *(const float4*)&As[k][m0];
            *(float4*)&a[4] = *(const float4*)&As[k][m0 + 4];
            *(float4*)&b[0] = *(const float4*)&Bs[k][n0];
            *(float4*)&b[4] = *(const float4*)&Bs[k][n0 + 4];
            #pragma unroll
            for (int i = 0; i < 8; i++)
                #pragma unroll
                for (int j = 0; j < 8; j++)
                    acc[i][j] += a[i] * b[j];
        }
        __syncthreads();
    }

    // ---- epilogue ----
    #pragma unroll
    for (int i = 0; i < 8; i++) {
        int mg = bm + m0 + i;
        float bv = BIAS ? bias[mg] : 0.f;
        if (POOL) {
            // maxpool2 over the n axis; this thread owns 8 consecutive n = 4 pairs
            int cg = (bn + n0) >> 1;
            #pragma unroll
            for (int j = 0; j < 4; j++) {
                float v = fmaxf(acc[i][2 * j] + bv, acc[i][2 * j + 1] + bv);
                C[(long)mg * ldc + cg + j] = v;
            }
        } else {
            float4 v0 = make_float4(acc[i][0] + bv, acc[i][1] + bv,
                                    acc[i][2] + bv, acc[i][3] + bv);
            float4 v1 = make_float4(acc[i][4] + bv, acc[i][5] + bv,
                                    acc[i][6] + bv, acc[i][7] + bv);
            *(float4*)&C[(long)mg * ldc + bn + n0] = v0;
            *(float4*)&C[(long)mg * ldc + bn + n0 + 4] = v1;
        }
    }
}

// ---------------- softmax over rows of f (row length 2048) ------------------
__global__ __launch_bounds__(256)
void softmax_kernel(float* __restrict__ f)
{
    __shared__ float smax[8];
    __shared__ float ssum[8];

    float* p = f + (size_t)blockIdx.x * LK;
    int tid = threadIdx.x;
    int lane = tid & 31, warp = tid >> 5;

    float v[8];
    *(float4*)&v[0] = *(const float4*)&p[tid * 8];
    *(float4*)&v[4] = *(const float4*)&p[tid * 8 + 4];

    float m = v[0];
    #pragma unroll
    for (int i = 1; i < 8; i++) m = fmaxf(m, v[i]);
    #pragma unroll
    for (int o = 16; o; o >>= 1) m = fmaxf(m, __shfl_xor_sync(0xffffffffu, m, o));
    if (lane == 0) smax[warp] = m;
    __syncthreads();
    if (tid < 8) {
        float t = smax[tid];
        #pragma unroll
        for (int o = 4; o; o >>= 1) t = fmaxf(t, __shfl_xor_sync(0xffu, t, o));
        smax[tid] = t;
    }
    __syncthreads();
    m = smax[0];

    float s = 0.f;
    #pragma unroll
    for (int i = 0; i < 8; i++) { v[i] = __expf(v[i] - m); s += v[i]; }
    #pragma unroll
    for (int o = 16; o; o >>= 1) s += __shfl_xor_sync(0xffffffffu, s, o);
    if (lane == 0) ssum[warp] = s;
    __syncthreads();
    if (tid < 8) {
        float t = ssum[tid];
        #pragma unroll
        for (int o = 4; o; o >>= 1) t += __shfl_xor_sync(0xffu, t, o);
        ssum[tid] = t;
    }
    __syncthreads();
    float inv = 1.f / ssum[0];

    #pragma unroll
    for (int i = 0; i < 8; i++) v[i] *= inv;
    *(float4*)&p[tid * 8]     = *(float4*)&v[0];
    *(float4*)&p[tid * 8 + 4] = *(float4*)&v[4];
}

// ---------------- BatchNorm batch statistics (per channel) ------------------
__global__ __launch_bounds__(256)
void bn_stats_kernel(const float* __restrict__ z, float* __restrict__ mean,
                     float* __restrict__ var)
{
    __shared__ float ss_s[8], ss_q[8];
    int c = blockIdx.x;
    int tid = threadIdx.x;
    int lane = tid & 31, warp = tid >> 5;

    float s = 0.f, q = 0.f;
    for (int b = 0; b < BATCH; b++) {
        const float* p = z + ((long)b * CFULL + c) * LQ;
        for (int l = tid * 4; l < LQ; l += 256 * 4) {
            float4 v = *(const float4*)&p[l];
            s += v.x + v.y + v.z + v.w;
            q += v.x * v.x + v.y * v.y + v.z * v.z + v.w * v.w;
        }
    }
    #pragma unroll
    for (int o = 16; o; o >>= 1) {
        s += __shfl_xor_sync(0xffffffffu, s, o);
        q += __shfl_xor_sync(0xffffffffu, q, o);
    }
    if (lane == 0) { ss_s[warp] = s; ss_q[warp] = q; }
    __syncthreads();
    if (tid == 0) {
        float S = 0.f, Q = 0.f;
        #pragma unroll
        for (int w = 0; w < 8; w++) { S += ss_s[w]; Q += ss_q[w]; }
        const float invN = 1.f / (float)(BATCH * LQ);
        float mu = S * invN;
        mean[c] = mu;
        var[c] = Q * invN - mu * mu;
    }
}

// ---------------- fused BN apply + residual ---------------------------------
__global__ __launch_bounds__(256)
void bn_apply_kernel(const float* __restrict__ z, const float* __restrict__ x,
                     const float* __restrict__ gamma, const float* __restrict__ beta,
                     const float* __restrict__ mean, const float* __restrict__ var,
                     float* __restrict__ out)
{
    long i4 = (long)blockIdx.x * 256 + threadIdx.x;
    long base = i4 * 4;
    int c = (int)((base >> 12) & (CFULL - 1));   // L = 4096 = 2^12
    float scale = gamma[c] * rsqrtf(var[c] + 1e-5f);
    float shift = beta[c] - mean[c] * scale;
    float4 zv = *(const float4*)&z[base];
    float4 xv = *(const float4*)&x[base];
    float4 o;
    o.x = zv.x * scale + shift + xv.x;
    o.y = zv.y * scale + shift + xv.y;
    o.z = zv.z * scale + shift + xv.z;
    o.w = zv.w * scale + shift + xv.w;
    *(float4*)&out[base] = o;
}

// ---------------- launch ------------------------------------------------------
extern "C" void kernel_launch(void* const* d_in, const int* in_sizes, int n_in,
                              void* d_out, int out_size)
{
    const float* x       = (const float*)d_in[0];
    const float* theta_w = (const float*)d_in[1];
    const float* theta_b = (const float*)d_in[2];
    const float* phi_w   = (const float*)d_in[3];
    const float* phi_b   = (const float*)d_in[4];
    const float* g_w     = (const float*)d_in[5];
    const float* g_b     = (const float*)d_in[6];
    const float* wz_w    = (const float*)d_in[7];
    const float* wz_b    = (const float*)d_in[8];
    const float* gamma   = (const float*)d_in[9];
    const float* beta    = (const float*)d_in[10];
    float* out = (float*)d_out;

    float *theta, *phi, *gbuf, *f, *y, *z, *mean, *var;
    cudaGetSymbolAddress((void**)&theta, g_theta);
    cudaGetSymbolAddress((void**)&phi,   g_phi);
    cudaGetSymbolAddress((void**)&gbuf,  g_gbuf);
    cudaGetSymbolAddress((void**)&f,     g_f);
    cudaGetSymbolAddress((void**)&y,     g_y);
    cudaGetSymbolAddress((void**)&z,     g_z);
    cudaGetSymbolAddress((void**)&mean,  g_mean);
    cudaGetSymbolAddress((void**)&var,   g_var);

    dim3 blk(256);

    // theta = theta_w @ x + theta_b          [Ci, L] per batch
    gemm_kernel<0,0,0,1><<<dim3(LQ/BN, CI/BM, BATCH), blk>>>(
        theta_w, x, theta_b, theta, CI, LQ, CFULL, LQ,
        0L, (long)CFULL * LQ, (long)CI * LQ);

    // phi = maxpool2(phi_w @ x + phi_b)      [Ci, L/2] per batch
    gemm_kernel<0,0,1,1><<<dim3(LQ/BN, CI/BM, BATCH), blk>>>(
        phi_w, x, phi_b, phi, CI, LQ, CFULL, LK,
        0L, (long)CFULL * LQ, (long)CI * LK);

    // g = maxpool2(g_w @ x + g_b)            [Ci, L/2] per batch
    gemm_kernel<0,0,1,1><<<dim3(LQ/BN, CI/BM, BATCH), blk>>>(
        g_w, x, g_b, gbuf, CI, LQ, CFULL, LK,
        0L, (long)CFULL * LQ, (long)CI * LK);

    // f[q,k] = sum_c theta[c,q] phi[c,k]     [L, L/2] per batch  (TA: theta is [K,M])
    gemm_kernel<1,0,0,0><<<dim3(LK/BN, LQ/BM, BATCH), blk>>>(
        theta, phi, nullptr, f, LQ, LK, CI, LK,
        (long)CI * LQ, (long)CI * LK, (long)LQ * LK);

    // softmax over k (rows of f)
    softmax_kernel<<<BATCH * LQ, blk>>>(f);

    // y[c,q] = sum_k g[c,k] f[q,k]           [Ci, L] per batch  (TB: f is [N,K])
    gemm_kernel<0,1,0,0><<<dim3(LQ/BN, CI/BM, BATCH), blk>>>(
        gbuf, f, nullptr, y, CI, LQ, LK, LQ,
        (long)CI * LK, (long)LQ * LK, (long)CI * LQ);

    // z = wz_w @ y + wz_b                    [C, L] per batch
    gemm_kernel<0,0,0,1><<<dim3(LQ/BN, CFULL/BM, BATCH), blk>>>(
        wz_w, y, wz_b, z, CFULL, LQ, CI, LQ,
        0L, (long)CI * LQ, (long)CFULL * LQ);

    // BatchNorm statistics (training mode, biased variance)
    bn_stats_kernel<<<CFULL, blk>>>(z, mean, var);

    // out = BN(z) * gamma + beta + x
    bn_apply_kernel<<<(BATCH * CFULL * LQ) / (256 * 4), blk>>>(
        z, x, gamma, beta, mean, var, out);
}

// round 3
// speedup vs baseline: 2.7052x; 2.7052x over previous
#include <cuda_runtime.h>
#include <cuda_bf16.h>
#include <cstdint>

#define BATCH 8
#define CFULL 512
#define CI    256
#define LQ    4096
#define LK    2048

#define SWZ(x) ((x) ^ (((x) >> 3) & 0x70))

__device__ __forceinline__ uint32_t smem_u32(const void* p) {
    uint32_t a;
    asm("{ .reg .u64 t; cvta.to.shared.u64 t, %1; cvt.u32.u64 %0, t; }" : "=r"(a) : "l"(p));
    return a;
}

#define CPA(saddr, gptr) \
    asm volatile("cp.async.cg.shared.global [%0], [%1], 16;" :: "r"(saddr), "l"(gptr))
#define CP_COMMIT() asm volatile("cp.async.commit_group;" ::: "memory")
#define CP_WAIT1()  asm volatile("cp.async.wait_group 1;" ::: "memory")
#define CP_WAIT0()  asm volatile("cp.async.wait_group 0;" ::: "memory")

#define LDSM4(r0, r1, r2, r3, addr) \
    asm volatile("ldmatrix.sync.aligned.m8n8.x4.shared.b16 {%0,%1,%2,%3}, [%4];" \
        : "=r"(r0), "=r"(r1), "=r"(r2), "=r"(r3) : "r"(addr))

#define MMA16816(d, a0, a1, a2, a3, b0, b1) \
    asm volatile("mma.sync.aligned.m16n8k16.row.col.f32.bf16.bf16.f32 " \
        "{%0,%1,%2,%3}, {%4,%5,%6,%7}, {%8,%9}, {%0,%1,%2,%3};" \
        : "+f"((d)[0]), "+f"((d)[1]), "+f"((d)[2]), "+f"((d)[3]) \
        : "r"(a0), "r"(a1), "r"(a2), "r"(a3), "r"(b0), "r"(b1))

// --------------------------------------------------------------- scratch
__device__ __nv_bfloat16 g_xt    [(size_t)BATCH * LQ * 1024];     // xT split [B][L][2C]
__device__ __nv_bfloat16 g_thetaT[(size_t)BATCH * LQ * 512];      // [B][L][2Ci]
__device__ float         g_phiT  [(size_t)BATCH * LQ * CI];       // [B][L][Ci]
__device__ __nv_bfloat16 g_phiPT [(size_t)BATCH * LK * 512];      // [B][L/2][2Ci]
__device__ float         g_g     [(size_t)BATCH * CI * LQ];       // [B][Ci][L]
__device__ __nv_bfloat16 g_gP    [(size_t)BATCH * CI * 4096];     // [B][Ci][2*L/2]
__device__ float         g_f     [(size_t)BATCH * LQ * LK];       // [B][L][L/2]
__device__ __nv_bfloat16 g_fs    [(size_t)BATCH * LQ * 4096];     // [B][L][2*L/2]
__device__ __nv_bfloat16 g_yT    [(size_t)BATCH * LQ * 512];      // [B][L][2Ci]
__device__ float         g_z     [(size_t)BATCH * CFULL * LQ];    // [B][C][L]
__device__ __nv_bfloat16 g_wth   [CI * 1024];
__device__ __nv_bfloat16 g_wph   [CI * 1024];
__device__ __nv_bfloat16 g_wg    [CI * 1024];
__device__ __nv_bfloat16 g_wwz   [CFULL * 512];
__device__ float g_mean[CFULL];
__device__ float g_var [CFULL];

// --------------------------------------------------------------- HMMA GEMM
// D[M,N] = sum over 3 split terms of A[M,K_eff=2K split]*B[N,2K split]^T.
// A: [M][lda] bf16, hi cols [0,K) lo [K,2K).  B: [N][ldb] same.
// CTA tile 128x128, BK=64, 2-stage cp.async, 8 warps (2m x 4n), warp 64x32.
#define SM_BYTES 65536
template<int BIASM, int BIASN, int SPLIT>
__global__ __launch_bounds__(256, 2)
void mma_gemm(const __nv_bfloat16* __restrict__ A, const __nv_bfloat16* __restrict__ B,
              const float* __restrict__ bias, void* __restrict__ Cv,
              int K, int lda, int ldb, int ldc, int lo_off,
              long sA, long sB, long sC)
{
    extern __shared__ char smem[];
    const uint32_t sb = smem_u32(smem);
    const int tid = threadIdx.x;
    const int wid = tid >> 5;
    const int lane = tid & 31;
    const int bm = blockIdx.y * 128;
    const int bn = blockIdx.x * 128;
    A += (long)blockIdx.z * sA;
    B += (long)blockIdx.z * sB;

    // cp.async slots: A tile 128x64 bf16 = 1024 16B chunks, B same
    const __nv_bfloat16* agp[4]; uint32_t asw[4];
    const __nv_bfloat16* bgp[4]; uint32_t bsw[4];
    #pragma unroll
    for (int i = 0; i < 4; i++) {
        int idx = tid + i * 256, r = idx >> 3, c = idx & 7;
        uint32_t sw = SWZ(r * 128 + c * 16);
        agp[i] = A + (long)(bm + r) * lda + c * 8;  asw[i] = sw;
        bgp[i] = B + (long)(bn + r) * ldb + c * 8;  bsw[i] = sw + 16384;
    }

    // ldmatrix base addresses (within a stage buffer), ks folds in via XOR of ks*32
    const int wm = wid >> 2;        // 0..1  (m)
    const int wn = wid & 3;         // 0..3  (n)
    uint32_t abase[4], bbase[2];
    #pragma unroll
    for (int mi = 0; mi < 4; mi++) {
        int arow = wm * 64 + mi * 16 + (lane & 15);
        abase[mi] = (uint32_t)(arow * 128) + ((((lane >> 4) << 4)) ^ ((arow & 7) << 4));
    }
    #pragma unroll
    for (int j2 = 0; j2 < 2; j2++) {
        int brow = wn * 32 + j2 * 16 + (lane & 7) + ((lane >> 4) << 3);
        uint32_t bcol = ((lane >> 3) & 1) << 4;
        bbase[j2] = 16384u + (uint32_t)(brow * 128) + (bcol ^ ((brow & 7) << 4));
    }

    float acc[4][4][4];
    #pragma unroll
    for (int i = 0; i < 4; i++)
        #pragma unroll
        for (int j = 0; j < 4; j++)
            #pragma unroll
            for (int q = 0; q < 4; q++)
                acc[i][j][q] = 0.f;

    const int kper = K >> 6;            // K/64
    const int nIt = 3 * kper;

    // term schedule: (hi,hi), (hi,lo), (lo,hi)
    long ao = 0, bo = 0;
    {   // prologue: load stage 0 for it=0
        #pragma unroll
        for (int i = 0; i < 4; i++) CPA(sb + asw[i], agp[i]);
        #pragma unroll
        for (int i = 0; i < 4; i++) CPA(sb + bsw[i], bgp[i]);
        CP_COMMIT();
    }

    #pragma unroll 1
    for (int it = 0; it < nIt; ++it) {
        if (it + 1 < nIt) {
            int nx = it + 1;
            int term = nx / kper;
            int kk = (nx - term * kper) << 6;
            ao = ((term == 2) ? (long)K : 0L) + kk;
            bo = ((term == 1) ? (long)K : 0L) + kk;
            uint32_t stg = ((nx & 1) ? 32768u : 0u);
            #pragma unroll
            for (int i = 0; i < 4; i++) CPA(sb + stg + asw[i], agp[i] + ao);
            #pragma unroll
            for (int i = 0; i < 4; i++) CPA(sb + stg + bsw[i], bgp[i] + bo);
            CP_COMMIT();
            CP_WAIT1();
        } else {
            CP_WAIT0();
        }
        __syncthreads();

        const uint32_t st = sb + ((it & 1) ? 32768u : 0u);
        #pragma unroll
        for (int ks = 0; ks < 4; ks++) {
            const uint32_t kx = (uint32_t)(ks << 5);
            uint32_t bf[4][2];
            LDSM4(bf[0][0], bf[0][1], bf[1][0], bf[1][1], st + (bbase[0] ^ kx));
            LDSM4(bf[2][0], bf[2][1], bf[3][0], bf[3][1], st + (bbase[1] ^ kx));
            #pragma unroll
            for (int mi = 0; mi < 4; mi++) {
                uint32_t a0, a1, a2, a3;
                LDSM4(a0, a1, a2, a3, st + (abase[mi] ^ kx));
                #pragma unroll
                for (int nj = 0; nj < 4; nj++)
                    MMA16816(acc[mi][nj], a0, a1, a2, a3, bf[nj][0], bf[nj][1]);
            }
        }
        __syncthreads();
    }

    // ---------------- epilogue ----------------
    float* Cf = (float*)Cv + (long)blockIdx.z * sC;
    __nv_bfloat16* Cb = (__nv_bfloat16*)Cv + (long)blockIdx.z * sC;

    #pragma unroll
    for (int mi = 0; mi < 4; mi++) {
        const int m0 = bm + wm * 64 + mi * 16 + (lane >> 2);
        const int m1 = m0 + 8;
        const float bm0 = BIASM ? __ldg(&bias[m0]) : 0.f;
        const float bm1 = BIASM ? __ldg(&bias[m1]) : 0.f;
        #pragma unroll
        for (int nj = 0; nj < 4; nj++) {
            const int n = bn + wn * 32 + nj * 8 + (lane & 3) * 2;
            const float bn0 = BIASN ? __ldg(&bias[n])     : 0.f;
            const float bn1 = BIASN ? __ldg(&bias[n + 1]) : 0.f;
            float v00 = acc[mi][nj][0] + bm0 + bn0;
            float v01 = acc[mi][nj][1] + bm0 + bn1;
            float v10 = acc[mi][nj][2] + bm1 + bn0;
            float v11 = acc[mi][nj][3] + bm1 + bn1;
            if (SPLIT) {
                __nv_bfloat16 h00 = __float2bfloat16(v00), h01 = __float2bfloat16(v01);
                __nv_bfloat16 h10 = __float2bfloat16(v10), h11 = __float2bfloat16(v11);
                __nv_bfloat162 hh0; hh0.x = h00; hh0.y = h01;
                __nv_bfloat162 hh1; hh1.x = h10; hh1.y = h11;
                __nv_bfloat162 ll0;
                ll0.x = __float2bfloat16(v00 - __bfloat162float(h00));
                ll0.y = __float2bfloat16(v01 - __bfloat162float(h01));
                __nv_bfloat162 ll1;
                ll1.x = __float2bfloat16(v10 - __bfloat162float(h10));
                ll1.y = __float2bfloat16(v11 - __bfloat162float(h11));
                *(__nv_bfloat162*)&Cb[(long)m0 * ldc + n] = hh0;
                *(__nv_bfloat162*)&Cb[(long)m0 * ldc + lo_off + n] = ll0;
                *(__nv_bfloat162*)&Cb[(long)m1 * ldc + n] = hh1;
                *(__nv_bfloat162*)&Cb[(long)m1 * ldc + lo_off + n] = ll1;
            } else {
                *(float2*)&Cf[(long)m0 * ldc + n] = make_float2(v00, v01);
                *(float2*)&Cf[(long)m1 * ldc + n] = make_float2(v10, v11);
            }
        }
    }
}

// --------------------------------------------------------------- aux kernels
__device__ __forceinline__ void split_store(__nv_bfloat16* hi_p, __nv_bfloat16* lo_p, float v) {
    __nv_bfloat16 h = __float2bfloat16(v);
    *hi_p = h;
    *lo_p = __float2bfloat16(v - __bfloat162float(h));
}

__global__ __launch_bounds__(256)
void wsplit_kernel(const float* __restrict__ w, __nv_bfloat16* __restrict__ o, int R, int Kc)
{
    int i = blockIdx.x * 256 + threadIdx.x;
    if (i >= R * Kc) return;
    int r = i / Kc, k = i - r * Kc;
    split_store(&o[(long)r * 2 * Kc + k], &o[(long)r * 2 * Kc + Kc + k], w[i]);
}

__global__ __launch_bounds__(256)
void transpose_split_kernel(const float* __restrict__ x, __nv_bfloat16* __restrict__ xt)
{
    __shared__ float t[32][33];
    int b = blockIdx.z;
    int l0 = blockIdx.x * 32, c0 = blockIdx.y * 32;
    int tx = threadIdx.x & 31, ty = threadIdx.x >> 5;
    const float* px = x + ((long)b * CFULL + c0) * LQ + l0;
    #pragma unroll
    for (int i = 0; i < 32; i += 8) t[ty + i][tx] = px[(long)(ty + i) * LQ + tx];
    __syncthreads();
    __nv_bfloat16* po = xt + ((long)b * LQ + l0) * 1024 + c0;
    #pragma unroll
    for (int i = 0; i < 32; i += 8) {
        float v = t[tx][ty + i];
        split_store(&po[(long)(ty + i) * 1024 + tx],
                    &po[(long)(ty + i) * 1024 + 512 + tx], v);
    }
}

// phiT fp32 [B][4096][256] -> maxpool over L pairs -> split [B][2048][512]
__global__ __launch_bounds__(256)
void pool_rows_split_kernel(const float* __restrict__ in, __nv_bfloat16* __restrict__ out)
{
    long i = (long)blockIdx.x * 256 + threadIdx.x;        // B*2048*256
    int ci = (int)(i & 255);
    long bk = i >> 8;
    int kk = (int)(bk & 2047);
    int b  = (int)(bk >> 11);
    const float* p = in + ((long)b * LQ + 2 * kk) * CI + ci;
    float v = fmaxf(p[0], p[CI]);
    __nv_bfloat16* q = out + ((long)b * LK + kk) * 512;
    split_store(&q[ci], &q[256 + ci], v);
}

// g fp32 [B][256][4096] -> maxpool over L pairs -> split [B][256][4096]
__global__ __launch_bounds__(256)
void pool_cols_split_kernel(const float* __restrict__ in, __nv_bfloat16* __restrict__ out)
{
    long i = (long)blockIdx.x * 256 + threadIdx.x;        // B*256*2048
    int k = (int)(i & 2047);
    long bc = i >> 11;
    int c = (int)(bc & 255);
    int b = (int)(bc >> 8);
    float2 v2 = *(const float2*)(in + ((long)b * CI + c) * LQ + 2 * k);
    float v = fmaxf(v2.x, v2.y);
    __nv_bfloat16* q = out + ((long)b * CI + c) * 4096;
    split_store(&q[k], &q[2048 + k], v);
}

// softmax over rows of f (2048), write split bf16 [row][4096]
__global__ __launch_bounds__(256)
void softmax_split_kernel(const float* __restrict__ f, __nv_bfloat16* __restrict__ fs)
{
    __shared__ float sred[8];
    const float* p = f + (size_t)blockIdx.x * LK;
    __nv_bfloat16* q = fs + (size_t)blockIdx.x * 4096;
    int tid = threadIdx.x, lane = tid & 31, warp = tid >> 5;

    float v[8];
    *(float4*)&v[0] = *(const float4*)&p[tid * 8];
    *(float4*)&v[4] = *(const float4*)&p[tid * 8 + 4];

    float m = v[0];
    #pragma unroll
    for (int i = 1; i < 8; i++) m = fmaxf(m, v[i]);
    #pragma unroll
    for (int o = 16; o; o >>= 1) m = fmaxf(m, __shfl_xor_sync(~0u, m, o));
    if (lane == 0) sred[warp] = m;
    __syncthreads();
    if (tid < 8) {
        float t = sred[tid];
        #pragma unroll
        for (int o = 4; o; o >>= 1) t = fmaxf(t, __shfl_xor_sync(0xffu, t, o));
        sred[tid] = t;
    }
    __syncthreads();
    m = sred[0];
    __syncthreads();

    float ssum = 0.f;
    #pragma unroll
    for (int i = 0; i < 8; i++) { v[i] = __expf(v[i] - m); ssum += v[i]; }
    #pragma unroll
    for (int o = 16; o; o >>= 1) ssum += __shfl_xor_sync(~0u, ssum, o);
    if (lane == 0) sred[warp] = ssum;
    __syncthreads();
    if (tid < 8) {
        float t = sred[tid];
        #pragma unroll
        for (int o = 4; o; o >>= 1) t += __shfl_xor_sync(0xffu, t, o);
        sred[tid] = t;
    }
    __syncthreads();
    float inv = 1.f / sred[0];

    #pragma unroll
    for (int j = 0; j < 8; j += 2) {
        float v0 = v[j] * inv, v1 = v[j + 1] * inv;
        __nv_bfloat16 h0 = __float2bfloat16(v0), h1 = __float2bfloat16(v1);
        __nv_bfloat162 hh; hh.x = h0; hh.y = h1;
        __nv_bfloat162 ll;
        ll.x = __float2bfloat16(v0 - __bfloat162float(h0));
        ll.y = __float2bfloat16(v1 - __bfloat162float(h1));
        *(__nv_bfloat162*)&q[tid * 8 + j] = hh;
        *(__nv_bfloat162*)&q[2048 + tid * 8 + j] = ll;
    }
}

__global__ __launch_bounds__(256)
void bn_stats_kernel(const float* __restrict__ z, float* __restrict__ mean,
                     float* __restrict__ var)
{
    __shared__ float ss_s[8], ss_q[8];
    int c = blockIdx.x, tid = threadIdx.x, lane = tid & 31, warp = tid >> 5;
    float s = 0.f, q = 0.f;
    for (int b = 0; b < BATCH; b++) {
        const float* p = z + ((long)b * CFULL + c) * LQ;
        for (int l = tid * 4; l < LQ; l += 256 * 4) {
            float4 v = *(const float4*)&p[l];
            s += v.x + v.y + v.z + v.w;
            q += v.x * v.x + v.y * v.y + v.z * v.z + v.w * v.w;
        }
    }
    #pragma unroll
    for (int o = 16; o; o >>= 1) {
        s += __shfl_xor_sync(~0u, s, o);
        q += __shfl_xor_sync(~0u, q, o);
    }
    if (lane == 0) { ss_s[warp] = s; ss_q[warp] = q; }
    __syncthreads();
    if (tid == 0) {
        float S = 0.f, Q = 0.f;
        #pragma unroll
        for (int w = 0; w < 8; w++) { S += ss_s[w]; Q += ss_q[w]; }
        const float invN = 1.f / (float)(BATCH * LQ);
        float mu = S * invN;
        mean[c] = mu;
        var[c] = Q * invN - mu * mu;
    }
}

__global__ __launch_bounds__(256)
void bn_apply_kernel(const float* __restrict__ z, const float* __restrict__ x,
                     const float* __restrict__ gamma, const float* __restrict__ beta,
                     const float* __restrict__ mean, const float* __restrict__ var,
                     float* __restrict__ out)
{
    long base = ((long)blockIdx.x * 256 + threadIdx.x) * 4;
    int c = (int)((base >> 12) & (CFULL - 1));
    float scale = gamma[c] * rsqrtf(var[c] + 1e-5f);
    float shift = beta[c] - mean[c] * scale;
    float4 zv = *(const float4*)&z[base];
    float4 xv = *(const float4*)&x[base];
    float4 o;
    o.x = zv.x * scale + shift + xv.x;
    o.y = zv.y * scale + shift + xv.y;
    o.z = zv.z * scale + shift + xv.z;
    o.w = zv.w * scale + shift + xv.w;
    *(float4*)&out[base] = o;
}

// --------------------------------------------------------------- launch
extern "C" void kernel_launch(void* const* d_in, const int* in_sizes, int n_in,
                              void* d_out, int out_size)
{
    const float* x       = (const float*)d_in[0];
    const float* theta_w = (const float*)d_in[1];
    const float* theta_b = (const float*)d_in[2];
    const float* phi_w   = (const float*)d_in[3];
    const float* phi_b   = (const float*)d_in[4];
    const float* g_w     = (const float*)d_in[5];
    const float* g_b     = (const float*)d_in[6];
    const float* wz_w    = (const float*)d_in[7];
    const float* wz_b    = (const float*)d_in[8];
    const float* gamma   = (const float*)d_in[9];
    const float* beta    = (const float*)d_in[10];
    float* out = (float*)d_out;

    __nv_bfloat16 *xt, *thetaT, *phiPT, *gP, *fs, *yT, *wth, *wph, *wg, *wwz;
    float *phiT, *gbuf, *f, *z, *mean, *var;
    cudaGetSymbolAddress((void**)&xt,     g_xt);
    cudaGetSymbolAddress((void**)&thetaT, g_thetaT);
    cudaGetSymbolAddress((void**)&phiT,   g_phiT);
    cudaGetSymbolAddress((void**)&phiPT,  g_phiPT);
    cudaGetSymbolAddress((void**)&gbuf,   g_g);
    cudaGetSymbolAddress((void**)&gP,     g_gP);
    cudaGetSymbolAddress((void**)&f,      g_f);
    cudaGetSymbolAddress((void**)&fs,     g_fs);
    cudaGetSymbolAddress((void**)&yT,     g_yT);
    cudaGetSymbolAddress((void**)&z,      g_z);
    cudaGetSymbolAddress((void**)&wth,    g_wth);
    cudaGetSymbolAddress((void**)&wph,    g_wph);
    cudaGetSymbolAddress((void**)&wg,     g_wg);
    cudaGetSymbolAddress((void**)&wwz,    g_wwz);
    cudaGetSymbolAddress((void**)&mean,   g_mean);
    cudaGetSymbolAddress((void**)&var,    g_var);

    cudaFuncSetAttribute((const void*)mma_gemm<0,1,1>, cudaFuncAttributeMaxDynamicSharedMemorySize, SM_BYTES);
    cudaFuncSetAttribute((const void*)mma_gemm<0,1,0>, cudaFuncAttributeMaxDynamicSharedMemorySize, SM_BYTES);
    cudaFuncSetAttribute((const void*)mma_gemm<1,0,0>, cudaFuncAttributeMaxDynamicSharedMemorySize, SM_BYTES);
    cudaFuncSetAttribute((const void*)mma_gemm<0,0,0>, cudaFuncAttributeMaxDynamicSharedMemorySize, SM_BYTES);
    cudaFuncSetAttribute((const void*)mma_gemm<0,0,1>, cudaFuncAttributeMaxDynamicSharedMemorySize, SM_BYTES);

    dim3 blk(256);

    // weight splits
    wsplit_kernel<<<(CI * CFULL) / 256, blk>>>(theta_w, wth, CI, CFULL);
    wsplit_kernel<<<(CI * CFULL) / 256, blk>>>(phi_w,   wph, CI, CFULL);
    wsplit_kernel<<<(CI * CFULL) / 256, blk>>>(g_w,     wg,  CI, CFULL);
    wsplit_kernel<<<(CFULL * CI) / 256, blk>>>(wz_w,    wwz, CFULL, CI);

    // xT split
    transpose_split_kernel<<<dim3(LQ / 32, CFULL / 32, BATCH), blk>>>(x, xt);

    // thetaT[L,Ci] split = xT * theta_w^T  (+bias n)
    mma_gemm<0,1,1><<<dim3(2, 32, BATCH), blk, SM_BYTES>>>(
        xt, wth, theta_b, thetaT, 512, 1024, 1024, 512, 256,
        (long)LQ * 1024, 0L, (long)LQ * 512);

    // phiT[L,Ci] fp32 = xT * phi_w^T  (+bias n)
    mma_gemm<0,1,0><<<dim3(2, 32, BATCH), blk, SM_BYTES>>>(
        xt, wph, phi_b, phiT, 512, 1024, 1024, 256, 0,
        (long)LQ * 1024, 0L, (long)LQ * CI);

    // g[Ci,L] fp32 = g_w * xT^T  (+bias m)
    mma_gemm<1,0,0><<<dim3(32, 2, BATCH), blk, SM_BYTES>>>(
        wg, xt, g_b, gbuf, 512, 1024, 1024, LQ, 0,
        0L, (long)LQ * 1024, (long)CI * LQ);

    pool_rows_split_kernel<<<(BATCH * LK * CI) / 256, blk>>>(phiT, phiPT);
    pool_cols_split_kernel<<<(BATCH * CI * LK) / 256, blk>>>(gbuf, gP);

    // f[L,L/2] fp32 = thetaT * phiPT^T
    mma_gemm<0,0,0><<<dim3(16, 32, BATCH), blk, SM_BYTES>>>(
        thetaT, phiPT, nullptr, f, 256, 512, 512, LK, 0,
        (long)LQ * 512, (long)LK * 512, (long)LQ * LK);

    softmax_split_kernel<<<BATCH * LQ, blk>>>(f, fs);

    // yT[L,Ci] split = fs * gP^T
    mma_gemm<0,0,1><<<dim3(2, 32, BATCH), blk, SM_BYTES>>>(
        fs, gP, nullptr, yT, 2048, 4096, 4096, 512, 256,
        (long)LQ * 4096, (long)CI * 4096, (long)LQ * 512);

    // z[C,L] fp32 = wz_w * yT^T  (+bias m)
    mma_gemm<1,0,0><<<dim3(32, 4, BATCH), blk, SM_BYTES>>>(
        wwz, yT, wz_b, z, 256, 512, 512, LQ, 0,
        0L, (long)LQ * 512, (long)CFULL * LQ);

    bn_stats_kernel<<<CFULL, blk>>>(z, mean, var);
    bn_apply_kernel<<<(BATCH * CFULL * LQ) / (256 * 4), blk>>>(
        z, x, gamma, beta, mean, var, out);
}

// round 4
// speedup vs baseline: 2.7599x; 1.0202x over previous
#include <cuda_runtime.h>
#include <cuda_bf16.h>
#include <cstdint>

#define BATCH 8
#define CFULL 512
#define CI    256
#define LQ    4096
#define LK    2048

#define SWZ(x) ((x) ^ (((x) >> 3) & 0x70))

__device__ __forceinline__ uint32_t smem_u32(const void* p) {
    uint32_t a;
    asm("{ .reg .u64 t; cvta.to.shared.u64 t, %1; cvt.u32.u64 %0, t; }" : "=r"(a) : "l"(p));
    return a;
}

#define CPA(saddr, gptr) \
    asm volatile("cp.async.cg.shared.global [%0], [%1], 16;" :: "r"(saddr), "l"(gptr))
#define CP_COMMIT() asm volatile("cp.async.commit_group;" ::: "memory")
#define CP_WAIT1()  asm volatile("cp.async.wait_group 1;" ::: "memory")

#define LDSM4(r0, r1, r2, r3, addr) \
    asm volatile("ldmatrix.sync.aligned.m8n8.x4.shared.b16 {%0,%1,%2,%3}, [%4];" \
        : "=r"(r0), "=r"(r1), "=r"(r2), "=r"(r3) : "r"(addr))

#define MMA16816(d, a0, a1, a2, a3, b0, b1) \
    asm volatile("mma.sync.aligned.m16n8k16.row.col.f32.bf16.bf16.f32 " \
        "{%0,%1,%2,%3}, {%4,%5,%6,%7}, {%8,%9}, {%0,%1,%2,%3};" \
        : "+f"((d)[0]), "+f"((d)[1]), "+f"((d)[2]), "+f"((d)[3]) \
        : "r"(a0), "r"(a1), "r"(a2), "r"(a3), "r"(b0), "r"(b1))

// --------------------------------------------------------------- scratch
__device__ __nv_bfloat16 g_xt    [(size_t)BATCH * LQ * 1024];     // xT split [B][L][2C]
__device__ __nv_bfloat16 g_thetaT[(size_t)BATCH * LQ * 512];      // [B][L][2Ci]
__device__ __nv_bfloat16 g_phiPT [(size_t)BATCH * LK * 512];      // [B][L/2][2Ci]
__device__ __nv_bfloat16 g_gP    [(size_t)BATCH * CI * 4096];     // [B][Ci][2*L/2]
__device__ float         g_f     [(size_t)BATCH * LQ * LK];       // [B][L][L/2]
__device__ __nv_bfloat16 g_fs    [(size_t)BATCH * LQ * 4096];     // [B][L][2*L/2]
__device__ __nv_bfloat16 g_yT    [(size_t)BATCH * LQ * 512];      // [B][L][2Ci]
__device__ float         g_z     [(size_t)BATCH * CFULL * LQ];    // [B][C][L]
__device__ __nv_bfloat16 g_wth   [CI * 1024];
__device__ __nv_bfloat16 g_wph   [CI * 1024];
__device__ __nv_bfloat16 g_wg    [CI * 1024];
__device__ __nv_bfloat16 g_wwz   [CFULL * 512];
__device__ float g_mean[CFULL];
__device__ float g_var [CFULL];

// --------------------------------------------------------------- HMMA GEMM
// D[M,N] = sum over 3 split terms of A[M,2K split]*B[N,2K split]^T.
// CTA tile 128x128, BK=64, 3-stage cp.async (one sync/iter), 8 warps (2m x 4n).
// POOLM: maxpool over m pairs (phi).  POOLN: maxpool over n pairs (g).
#define SM_BYTES 98304
template<int BIASM, int BIASN, int SPLIT, int POOLM, int POOLN>
__global__ __launch_bounds__(256, 2)
void mma_gemm(const __nv_bfloat16* __restrict__ A, const __nv_bfloat16* __restrict__ B,
              const float* __restrict__ bias, void* __restrict__ Cv,
              int K, int lda, int ldb, int ldc, int lo_off,
              long sA, long sB, long sC)
{
    extern __shared__ char smem[];
    const uint32_t sb = smem_u32(smem);
    const int tid = threadIdx.x;
    const int wid = tid >> 5;
    const int lane = tid & 31;
    const int bm = blockIdx.y * 128;
    const int bn = blockIdx.x * 128;
    A += (long)blockIdx.z * sA;
    B += (long)blockIdx.z * sB;

    const __nv_bfloat16* agp[4]; uint32_t asw[4];
    const __nv_bfloat16* bgp[4]; uint32_t bsw[4];
    #pragma unroll
    for (int i = 0; i < 4; i++) {
        int idx = tid + i * 256, r = idx >> 3, c = idx & 7;
        uint32_t sw = SWZ(r * 128 + c * 16);
        agp[i] = A + (long)(bm + r) * lda + c * 8;  asw[i] = sw;
        bgp[i] = B + (long)(bn + r) * ldb + c * 8;  bsw[i] = sw + 16384;
    }

    const int wm = wid >> 2;        // 0..1
    const int wn = wid & 3;         // 0..3
    uint32_t abase[4], bbase[2];
    #pragma unroll
    for (int mi = 0; mi < 4; mi++) {
        int arow = wm * 64 + mi * 16 + (lane & 15);
        abase[mi] = (uint32_t)(arow * 128) + ((((lane >> 4) << 4)) ^ ((arow & 7) << 4));
    }
    #pragma unroll
    for (int j2 = 0; j2 < 2; j2++) {
        int brow = wn * 32 + j2 * 16 + (lane & 7) + ((lane >> 4) << 3);
        uint32_t bcol = ((lane >> 3) & 1) << 4;
        bbase[j2] = 16384u + (uint32_t)(brow * 128) + (bcol ^ ((brow & 7) << 4));
    }

    float acc[4][4][4];
    #pragma unroll
    for (int i = 0; i < 4; i++)
        #pragma unroll
        for (int j = 0; j < 4; j++)
            #pragma unroll
            for (int q = 0; q < 4; q++)
                acc[i][j][q] = 0.f;

    const int kper = K >> 6;
    const int nIt = 3 * kper;

    // offsets for iteration n: term schedule (hi,hi),(hi,lo),(lo,hi)
    auto offs = [&](int n, long& ao, long& bo) {
        int term = n / kper;
        int kk = (n - term * kper) << 6;
        ao = ((term == 2) ? (long)K : 0L) + kk;
        bo = ((term == 1) ? (long)K : 0L) + kk;
    };

    // prologue: stages 0 and 1
    {
        long ao, bo;
        offs(0, ao, bo);
        #pragma unroll
        for (int i = 0; i < 4; i++) CPA(sb + asw[i], agp[i] + ao);
        #pragma unroll
        for (int i = 0; i < 4; i++) CPA(sb + bsw[i], bgp[i] + bo);
        CP_COMMIT();
        if (1 < nIt) {
            offs(1, ao, bo);
            #pragma unroll
            for (int i = 0; i < 4; i++) CPA(sb + 32768u + asw[i], agp[i] + ao);
            #pragma unroll
            for (int i = 0; i < 4; i++) CPA(sb + 32768u + bsw[i], bgp[i] + bo);
        }
        CP_COMMIT();
    }

    int cur = 0;                    // stage of iteration it
    #pragma unroll 1
    for (int it = 0; it < nIt; ++it) {
        CP_WAIT1();                 // stage `cur` data ready
        __syncthreads();            // all warps done with stage being overwritten

        const uint32_t st = sb + (uint32_t)cur * 32768u;
        #pragma unroll
        for (int ks = 0; ks < 4; ks++) {
            const uint32_t kx = (uint32_t)(ks << 5);
            uint32_t bf[4][2];
            LDSM4(bf[0][0], bf[0][1], bf[1][0], bf[1][1], st + (bbase[0] ^ kx));
            LDSM4(bf[2][0], bf[2][1], bf[3][0], bf[3][1], st + (bbase[1] ^ kx));
            #pragma unroll
            for (int mi = 0; mi < 4; mi++) {
                uint32_t a0, a1, a2, a3;
                LDSM4(a0, a1, a2, a3, st + (abase[mi] ^ kx));
                #pragma unroll
                for (int nj = 0; nj < 4; nj++)
                    MMA16816(acc[mi][nj], a0, a1, a2, a3, bf[nj][0], bf[nj][1]);
            }
        }

        // issue stage it+2 (safe: all warps passed this iter's sync, so all
        // finished reading buffer (it-1)%3 == (it+2)%3 in iteration it-1)
        if (it + 2 < nIt) {
            long ao, bo;
            offs(it + 2, ao, bo);
            int nst = cur + 2; if (nst >= 3) nst -= 3;
            uint32_t stg = (uint32_t)nst * 32768u;
            #pragma unroll
            for (int i = 0; i < 4; i++) CPA(sb + stg + asw[i], agp[i] + ao);
            #pragma unroll
            for (int i = 0; i < 4; i++) CPA(sb + stg + bsw[i], bgp[i] + bo);
        }
        CP_COMMIT();                // commit (possibly empty) keeps group count uniform
        if (++cur == 3) cur = 0;
    }

    // ---------------- epilogue ----------------
    float* Cf = (float*)Cv + (long)blockIdx.z * sC;
    __nv_bfloat16* Cb = (__nv_bfloat16*)Cv + (long)blockIdx.z * sC;

    #pragma unroll
    for (int mi = 0; mi < 4; mi++) {
        const int m0 = bm + wm * 64 + mi * 16 + (lane >> 2);
        const int m1 = m0 + 8;
        const float bm0 = BIASM ? __ldg(&bias[m0]) : 0.f;
        const float bm1 = BIASM ? __ldg(&bias[m1]) : 0.f;
        #pragma unroll
        for (int nj = 0; nj < 4; nj++) {
            const int n = bn + wn * 32 + nj * 8 + (lane & 3) * 2;
            const float bn0 = BIASN ? __ldg(&bias[n])     : 0.f;
            const float bn1 = BIASN ? __ldg(&bias[n + 1]) : 0.f;
            float v00 = acc[mi][nj][0] + bm0 + bn0;
            float v01 = acc[mi][nj][1] + bm0 + bn1;
            float v10 = acc[mi][nj][2] + bm1 + bn0;
            float v11 = acc[mi][nj][3] + bm1 + bn1;
            if (POOLM) {
                // pool over m pairs: rows (2r,2r+1) sit in lanes differing by bit 2
                float p00 = fmaxf(v00, __shfl_xor_sync(~0u, v00, 4));
                float p01 = fmaxf(v01, __shfl_xor_sync(~0u, v01, 4));
                float p10 = fmaxf(v10, __shfl_xor_sync(~0u, v10, 4));
                float p11 = fmaxf(v11, __shfl_xor_sync(~0u, v11, 4));
                if (!(lane & 4)) {
                    int pr0 = m0 >> 1, pr1 = m1 >> 1;
                    __nv_bfloat16 h0 = __float2bfloat16(p00), h1 = __float2bfloat16(p01);
                    __nv_bfloat16 h2 = __float2bfloat16(p10), h3 = __float2bfloat16(p11);
                    __nv_bfloat162 hh0; hh0.x = h0; hh0.y = h1;
                    __nv_bfloat162 hh1; hh1.x = h2; hh1.y = h3;
                    __nv_bfloat162 ll0;
                    ll0.x = __float2bfloat16(p00 - __bfloat162float(h0));
                    ll0.y = __float2bfloat16(p01 - __bfloat162float(h1));
                    __nv_bfloat162 ll1;
                    ll1.x = __float2bfloat16(p10 - __bfloat162float(h2));
                    ll1.y = __float2bfloat16(p11 - __bfloat162float(h3));
                    *(__nv_bfloat162*)&Cb[(long)pr0 * ldc + n] = hh0;
                    *(__nv_bfloat162*)&Cb[(long)pr0 * ldc + lo_off + n] = ll0;
                    *(__nv_bfloat162*)&Cb[(long)pr1 * ldc + n] = hh1;
                    *(__nv_bfloat162*)&Cb[(long)pr1 * ldc + lo_off + n] = ll1;
                }
            } else if (POOLN) {
                // pool over n pairs: v.0/v.1 are adjacent columns in-thread
                float p0 = fmaxf(v00, v01);
                float p1 = fmaxf(v10, v11);
                int np = n >> 1;
                __nv_bfloat16 h0 = __float2bfloat16(p0);
                __nv_bfloat16 h1 = __float2bfloat16(p1);
                Cb[(long)m0 * ldc + np] = h0;
                Cb[(long)m0 * ldc + lo_off + np] = __float2bfloat16(p0 - __bfloat162float(h0));
                Cb[(long)m1 * ldc + np] = h1;
                Cb[(long)m1 * ldc + lo_off + np] = __float2bfloat16(p1 - __bfloat162float(h1));
            } else if (SPLIT) {
                __nv_bfloat16 h00 = __float2bfloat16(v00), h01 = __float2bfloat16(v01);
                __nv_bfloat16 h10 = __float2bfloat16(v10), h11 = __float2bfloat16(v11);
                __nv_bfloat162 hh0; hh0.x = h00; hh0.y = h01;
                __nv_bfloat162 hh1; hh1.x = h10; hh1.y = h11;
                __nv_bfloat162 ll0;
                ll0.x = __float2bfloat16(v00 - __bfloat162float(h00));
                ll0.y = __float2bfloat16(v01 - __bfloat162float(h01));
                __nv_bfloat162 ll1;
                ll1.x = __float2bfloat16(v10 - __bfloat162float(h10));
                ll1.y = __float2bfloat16(v11 - __bfloat162float(h11));
                *(__nv_bfloat162*)&Cb[(long)m0 * ldc + n] = hh0;
                *(__nv_bfloat162*)&Cb[(long)m0 * ldc + lo_off + n] = ll0;
                *(__nv_bfloat162*)&Cb[(long)m1 * ldc + n] = hh1;
                *(__nv_bfloat162*)&Cb[(long)m1 * ldc + lo_off + n] = ll1;
            } else {
                *(float2*)&Cf[(long)m0 * ldc + n] = make_float2(v00, v01);
                *(float2*)&Cf[(long)m1 * ldc + n] = make_float2(v10, v11);
            }
        }
    }
}

// --------------------------------------------------------------- aux kernels
__device__ __forceinline__ void split_store(__nv_bfloat16* hi_p, __nv_bfloat16* lo_p, float v) {
    __nv_bfloat16 h = __float2bfloat16(v);
    *hi_p = h;
    *lo_p = __float2bfloat16(v - __bfloat162float(h));
}

// all 4 weights in one launch (each is 131072 elements)
__global__ __launch_bounds__(256)
void wsplit_all_kernel(const float* __restrict__ tw, const float* __restrict__ pw,
                       const float* __restrict__ gw, const float* __restrict__ zw,
                       __nv_bfloat16* __restrict__ ot, __nv_bfloat16* __restrict__ op,
                       __nv_bfloat16* __restrict__ og, __nv_bfloat16* __restrict__ oz)
{
    int i = blockIdx.x * 256 + threadIdx.x;
    int which = i >> 17;
    int j = i & 131071;
    const float* w; __nv_bfloat16* o; int Kc;
    if      (which == 0) { w = tw; o = ot; Kc = 512; }
    else if (which == 1) { w = pw; o = op; Kc = 512; }
    else if (which == 2) { w = gw; o = og; Kc = 512; }
    else                 { w = zw; o = oz; Kc = 256; }
    int r = j / Kc, k = j - r * Kc;
    split_store(&o[(long)r * 2 * Kc + k], &o[(long)r * 2 * Kc + Kc + k], w[j]);
}

__global__ __launch_bounds__(256)
void transpose_split_kernel(const float* __restrict__ x, __nv_bfloat16* __restrict__ xt)
{
    __shared__ float t[32][33];
    int b = blockIdx.z;
    int l0 = blockIdx.x * 32, c0 = blockIdx.y * 32;
    int tx = threadIdx.x & 31, ty = threadIdx.x >> 5;
    const float* px = x + ((long)b * CFULL + c0) * LQ + l0;
    #pragma unroll
    for (int i = 0; i < 32; i += 8) t[ty + i][tx] = px[(long)(ty + i) * LQ + tx];
    __syncthreads();
    __nv_bfloat16* po = xt + ((long)b * LQ + l0) * 1024 + c0;
    #pragma unroll
    for (int i = 0; i < 32; i += 8) {
        float v = t[tx][ty + i];
        split_store(&po[(long)(ty + i) * 1024 + tx],
                    &po[(long)(ty + i) * 1024 + 512 + tx], v);
    }
}

// softmax over rows of f (2048), write split bf16 [row][4096]
__global__ __launch_bounds__(256)
void softmax_split_kernel(const float* __restrict__ f, __nv_bfloat16* __restrict__ fs)
{
    __shared__ float sred[8];
    const float* p = f + (size_t)blockIdx.x * LK;
    __nv_bfloat16* q = fs + (size_t)blockIdx.x * 4096;
    int tid = threadIdx.x, lane = tid & 31, warp = tid >> 5;

    float v[8];
    *(float4*)&v[0] = *(const float4*)&p[tid * 8];
    *(float4*)&v[4] = *(const float4*)&p[tid * 8 + 4];

    float m = v[0];
    #pragma unroll
    for (int i = 1; i < 8; i++) m = fmaxf(m, v[i]);
    #pragma unroll
    for (int o = 16; o; o >>= 1) m = fmaxf(m, __shfl_xor_sync(~0u, m, o));
    if (lane == 0) sred[warp] = m;
    __syncthreads();
    if (tid < 8) {
        float t = sred[tid];
        #pragma unroll
        for (int o = 4; o; o >>= 1) t = fmaxf(t, __shfl_xor_sync(0xffu, t, o));
        sred[tid] = t;
    }
    __syncthreads();
    m = sred[0];
    __syncthreads();

    float ssum = 0.f;
    #pragma unroll
    for (int i = 0; i < 8; i++) { v[i] = __expf(v[i] - m); ssum += v[i]; }
    #pragma unroll
    for (int o = 16; o; o >>= 1) ssum += __shfl_xor_sync(~0u, ssum, o);
    if (lane == 0) sred[warp] = ssum;
    __syncthreads();
    if (tid < 8) {
        float t = sred[tid];
        #pragma unroll
        for (int o = 4; o; o >>= 1) t += __shfl_xor_sync(0xffu, t, o);
        sred[tid] = t;
    }
    __syncthreads();
    float inv = 1.f / sred[0];

    #pragma unroll
    for (int j = 0; j < 8; j += 2) {
        float v0 = v[j] * inv, v1 = v[j + 1] * inv;
        __nv_bfloat16 h0 = __float2bfloat16(v0), h1 = __float2bfloat16(v1);
        __nv_bfloat162 hh; hh.x = h0; hh.y = h1;
        __nv_bfloat162 ll;
        ll.x = __float2bfloat16(v0 - __bfloat162float(h0));
        ll.y = __float2bfloat16(v1 - __bfloat162float(h1));
        *(__nv_bfloat162*)&q[tid * 8 + j] = hh;
        *(__nv_bfloat162*)&q[2048 + tid * 8 + j] = ll;
    }
}

__global__ __launch_bounds__(256)
void bn_stats_kernel(const float* __restrict__ z, float* __restrict__ mean,
                     float* __restrict__ var)
{
    __shared__ float ss_s[8], ss_q[8];
    int c = blockIdx.x, tid = threadIdx.x, lane = tid & 31, warp = tid >> 5;
    float s = 0.f, q = 0.f;
    for (int b = 0; b < BATCH; b++) {
        const float* p = z + ((long)b * CFULL + c) * LQ;
        for (int l = tid * 4; l < LQ; l += 256 * 4) {
            float4 v = *(const float4*)&p[l];
            s += v.x + v.y + v.z + v.w;
            q += v.x * v.x + v.y * v.y + v.z * v.z + v.w * v.w;
        }
    }
    #pragma unroll
    for (int o = 16; o; o >>= 1) {
        s += __shfl_xor_sync(~0u, s, o);
        q += __shfl_xor_sync(~0u, q, o);
    }
    if (lane == 0) { ss_s[warp] = s; ss_q[warp] = q; }
    __syncthreads();
    if (tid == 0) {
        float S = 0.f, Q = 0.f;
        #pragma unroll
        for (int w = 0; w < 8; w++) { S += ss_s[w]; Q += ss_q[w]; }
        const float invN = 1.f / (float)(BATCH * LQ);
        float mu = S * invN;
        mean[c] = mu;
        var[c] = Q * invN - mu * mu;
    }
}

__global__ __launch_bounds__(256)
void bn_apply_kernel(const float* __restrict__ z, const float* __restrict__ x,
                     const float* __restrict__ gamma, const float* __restrict__ beta,
                     const float* __restrict__ mean, const float* __restrict__ var,
                     float* __restrict__ out)
{
    long base = ((long)blockIdx.x * 256 + threadIdx.x) * 4;
    int c = (int)((base >> 12) & (CFULL - 1));
    float scale = gamma[c] * rsqrtf(var[c] + 1e-5f);
    float shift = beta[c] - mean[c] * scale;
    float4 zv = *(const float4*)&z[base];
    float4 xv = *(const float4*)&x[base];
    float4 o;
    o.x = zv.x * scale + shift + xv.x;
    o.y = zv.y * scale + shift + xv.y;
    o.z = zv.z * scale + shift + xv.z;
    o.w = zv.w * scale + shift + xv.w;
    *(float4*)&out[base] = o;
}

// --------------------------------------------------------------- launch
extern "C" void kernel_launch(void* const* d_in, const int* in_sizes, int n_in,
                              void* d_out, int out_size)
{
    const float* x       = (const float*)d_in[0];
    const float* theta_w = (const float*)d_in[1];
    const float* theta_b = (const float*)d_in[2];
    const float* phi_w   = (const float*)d_in[3];
    const float* phi_b   = (const float*)d_in[4];
    const float* g_w     = (const float*)d_in[5];
    const float* g_b     = (const float*)d_in[6];
    const float* wz_w    = (const float*)d_in[7];
    const float* wz_b    = (const float*)d_in[8];
    const float* gamma   = (const float*)d_in[9];
    const float* beta    = (const float*)d_in[10];
    float* out = (float*)d_out;

    __nv_bfloat16 *xt, *thetaT, *phiPT, *gP, *fs, *yT, *wth, *wph, *wg, *wwz;
    float *f, *z, *mean, *var;
    cudaGetSymbolAddress((void**)&xt,     g_xt);
    cudaGetSymbolAddress((void**)&thetaT, g_thetaT);
    cudaGetSymbolAddress((void**)&phiPT,  g_phiPT);
    cudaGetSymbolAddress((void**)&gP,     g_gP);
    cudaGetSymbolAddress((void**)&f,      g_f);
    cudaGetSymbolAddress((void**)&fs,     g_fs);
    cudaGetSymbolAddress((void**)&yT,     g_yT);
    cudaGetSymbolAddress((void**)&z,      g_z);
    cudaGetSymbolAddress((void**)&wth,    g_wth);
    cudaGetSymbolAddress((void**)&wph,    g_wph);
    cudaGetSymbolAddress((void**)&wg,     g_wg);
    cudaGetSymbolAddress((void**)&wwz,    g_wwz);
    cudaGetSymbolAddress((void**)&mean,   g_mean);
    cudaGetSymbolAddress((void**)&var,    g_var);

    cudaFuncSetAttribute((const void*)mma_gemm<0,1,1,0,0>, cudaFuncAttributeMaxDynamicSharedMemorySize, SM_BYTES);
    cudaFuncSetAttribute((const void*)mma_gemm<0,1,1,1,0>, cudaFuncAttributeMaxDynamicSharedMemorySize, SM_BYTES);
    cudaFuncSetAttribute((const void*)mma_gemm<1,0,1,0,1>, cudaFuncAttributeMaxDynamicSharedMemorySize, SM_BYTES);
    cudaFuncSetAttribute((const void*)mma_gemm<0,0,0,0,0>, cudaFuncAttributeMaxDynamicSharedMemorySize, SM_BYTES);
    cudaFuncSetAttribute((const void*)mma_gemm<0,0,1,0,0>, cudaFuncAttributeMaxDynamicSharedMemorySize, SM_BYTES);
    cudaFuncSetAttribute((const void*)mma_gemm<1,0,0,0,0>, cudaFuncAttributeMaxDynamicSharedMemorySize, SM_BYTES);

    dim3 blk(256);

    // all weight splits, one launch
    wsplit_all_kernel<<<2048, blk>>>(theta_w, phi_w, g_w, wz_w, wth, wph, wg, wwz);

    // xT split
    transpose_split_kernel<<<dim3(LQ / 32, CFULL / 32, BATCH), blk>>>(x, xt);

    // thetaT[L,Ci] split = xT * theta_w^T  (+bias n)
    mma_gemm<0,1,1,0,0><<<dim3(2, 32, BATCH), blk, SM_BYTES>>>(
        xt, wth, theta_b, thetaT, 512, 1024, 1024, 512, 256,
        (long)LQ * 1024, 0L, (long)LQ * 512);

    // phiP[L/2,Ci] split = maxpool_m(xT * phi_w^T + bias n)
    mma_gemm<0,1,1,1,0><<<dim3(2, 32, BATCH), blk, SM_BYTES>>>(
        xt, wph, phi_b, phiPT, 512, 1024, 1024, 512, 256,
        (long)LQ * 1024, 0L, (long)LK * 512);

    // gP[Ci,L/2] split = maxpool_n(g_w * xT^T + bias m)
    mma_gemm<1,0,1,0,1><<<dim3(32, 2, BATCH), blk, SM_BYTES>>>(
        wg, xt, g_b, gP, 512, 1024, 1024, 4096, 2048,
        0L, (long)LQ * 1024, (long)CI * 4096);

    // f[L,L/2] fp32 = thetaT * phiP^T
    mma_gemm<0,0,0,0,0><<<dim3(16, 32, BATCH), blk, SM_BYTES>>>(
        thetaT, phiPT, nullptr, f, 256, 512, 512, LK, 0,
        (long)LQ * 512, (long)LK * 512, (long)LQ * LK);

    softmax_split_kernel<<<BATCH * LQ, blk>>>(f, fs);

    // yT[L,Ci] split = fs * gP^T
    mma_gemm<0,0,1,0,0><<<dim3(2, 32, BATCH), blk, SM_BYTES>>>(
        fs, gP, nullptr, yT, 2048, 4096, 4096, 512, 256,
        (long)LQ * 4096, (long)CI * 4096, (long)LQ * 512);

    // z[C,L] fp32 = wz_w * yT^T  (+bias m)
    mma_gemm<1,0,0,0,0><<<dim3(32, 4, BATCH), blk, SM_BYTES>>>(
        wwz, yT, wz_b, z, 256, 512, 512, LQ, 0,
        0L, (long)LQ * 512, (long)CFULL * LQ);

    bn_stats_kernel<<<CFULL, blk>>>(z, mean, var);
    bn_apply_kernel<<<(BATCH * CFULL * LQ) / (256 * 4), blk>>>(
        z, x, gamma, beta, mean, var, out);
}

// round 5
// speedup vs baseline: 2.8563x; 1.0349x over previous
#include <cuda_runtime.h>
#include <cuda_bf16.h>
#include <cstdint>

#define BATCH 8
#define CFULL 512
#define CI    256
#define LQ    4096
#define LK    2048

#define SWZ(x) ((x) ^ (((x) >> 3) & 0x70))

__device__ __forceinline__ uint32_t smem_u32(const void* p) {
    uint32_t a;
    asm("{ .reg .u64 t; cvta.to.shared.u64 t, %1; cvt.u32.u64 %0, t; }" : "=r"(a) : "l"(p));
    return a;
}

#define CPA(saddr, gptr) \
    asm volatile("cp.async.cg.shared.global [%0], [%1], 16;" :: "r"(saddr), "l"(gptr))
#define CP_COMMIT() asm volatile("cp.async.commit_group;" ::: "memory")
#define CP_WAIT1()  asm volatile("cp.async.wait_group 1;" ::: "memory")

#define LDSM4(r0, r1, r2, r3, addr) \
    asm volatile("ldmatrix.sync.aligned.m8n8.x4.shared.b16 {%0,%1,%2,%3}, [%4];" \
        : "=r"(r0), "=r"(r1), "=r"(r2), "=r"(r3) : "r"(addr))

#define MMA16816(d, a0, a1, a2, a3, b0, b1) \
    asm volatile("mma.sync.aligned.m16n8k16.row.col.f32.bf16.bf16.f32 " \
        "{%0,%1,%2,%3}, {%4,%5,%6,%7}, {%8,%9}, {%0,%1,%2,%3};" \
        : "+f"((d)[0]), "+f"((d)[1]), "+f"((d)[2]), "+f"((d)[3]) \
        : "r"(a0), "r"(a1), "r"(a2), "r"(a3), "r"(b0), "r"(b1))

// --------------------------------------------------------------- scratch
__device__ __nv_bfloat16 g_xt    [(size_t)BATCH * LQ * 1024];     // xT split [B][L][2C]
__device__ __nv_bfloat16 g_thetaT[(size_t)BATCH * LQ * 512];      // [B][L][2Ci]
__device__ __nv_bfloat16 g_phiPT [(size_t)BATCH * LK * 512];      // [B][L/2][2Ci]
__device__ __nv_bfloat16 g_gP    [(size_t)BATCH * CI * 4096];     // [B][Ci][2*L/2]
__device__ __nv_bfloat16 g_fs    [(size_t)BATCH * LQ * 4096];     // exp(f) split [B][L][2*L/2]
__device__ float         g_psum  [(size_t)BATCH * LQ * 64];       // partial row sums
__device__ float         g_inv   [(size_t)BATCH * LQ];            // 1/rowsum
__device__ __nv_bfloat16 g_yT    [(size_t)BATCH * LQ * 512];      // [B][L][2Ci]
__device__ float         g_z     [(size_t)BATCH * CFULL * LQ];    // [B][C][L]
__device__ __nv_bfloat16 g_wth   [CI * 1024];
__device__ __nv_bfloat16 g_wph   [CI * 1024];
__device__ __nv_bfloat16 g_wg    [CI * 1024];
__device__ __nv_bfloat16 g_wwz   [CFULL * 512];
__device__ float g_mean[CFULL];
__device__ float g_var [CFULL];

// --------------------------------------------------------------- HMMA GEMM
// D[M,N] = sum over 3 split terms of A[M,2K split]*B[N,2K split]^T.
// CTA tile 128x128, BK=64, 3-stage cp.async, 8 warps (2m x 4n).
// POOLM/POOLN: fused maxpool2.  SOFTEXP: exp + split write + row partial sums.
// SCALEM: multiply row m by scalev[m] before split write.
#define SM_BYTES 98304
template<int BIASM, int BIASN, int SPLIT, int POOLM, int POOLN, int SOFTEXP, int SCALEM>
__global__ __launch_bounds__(256, 2)
void mma_gemm(const __nv_bfloat16* __restrict__ A, const __nv_bfloat16* __restrict__ B,
              const float* __restrict__ bias, const float* __restrict__ scalev,
              float* __restrict__ psum, void* __restrict__ Cv,
              int K, int lda, int ldb, int ldc, int lo_off,
              long sA, long sB, long sC)
{
    extern __shared__ char smem[];
    const uint32_t sb = smem_u32(smem);
    const int tid = threadIdx.x;
    const int wid = tid >> 5;
    const int lane = tid & 31;
    const int bm = blockIdx.y * 128;
    const int bn = blockIdx.x * 128;
    A += (long)blockIdx.z * sA;
    B += (long)blockIdx.z * sB;

    const __nv_bfloat16* agp[4]; uint32_t asw[4];
    const __nv_bfloat16* bgp[4]; uint32_t bsw[4];
    #pragma unroll
    for (int i = 0; i < 4; i++) {
        int idx = tid + i * 256, r = idx >> 3, c = idx & 7;
        uint32_t sw = SWZ(r * 128 + c * 16);
        agp[i] = A + (long)(bm + r) * lda + c * 8;  asw[i] = sw;
        bgp[i] = B + (long)(bn + r) * ldb + c * 8;  bsw[i] = sw + 16384;
    }

    const int wm = wid >> 2;        // 0..1
    const int wn = wid & 3;         // 0..3
    uint32_t abase[4], bbase[2];
    #pragma unroll
    for (int mi = 0; mi < 4; mi++) {
        int arow = wm * 64 + mi * 16 + (lane & 15);
        abase[mi] = (uint32_t)(arow * 128) + ((((lane >> 4) << 4)) ^ ((arow & 7) << 4));
    }
    #pragma unroll
    for (int j2 = 0; j2 < 2; j2++) {
        int brow = wn * 32 + j2 * 16 + (lane & 7) + ((lane >> 4) << 3);
        uint32_t bcol = ((lane >> 3) & 1) << 4;
        bbase[j2] = 16384u + (uint32_t)(brow * 128) + (bcol ^ ((brow & 7) << 4));
    }

    float acc[4][4][4];
    #pragma unroll
    for (int i = 0; i < 4; i++)
        #pragma unroll
        for (int j = 0; j < 4; j++)
            #pragma unroll
            for (int q = 0; q < 4; q++)
                acc[i][j][q] = 0.f;

    const int kper = K >> 6;
    const int nIt = 3 * kper;

    auto offs = [&](int n, long& ao, long& bo) {
        int term = n / kper;
        int kk = (n - term * kper) << 6;
        ao = ((term == 2) ? (long)K : 0L) + kk;
        bo = ((term == 1) ? (long)K : 0L) + kk;
    };

    // prologue: stages 0 and 1
    {
        long ao, bo;
        offs(0, ao, bo);
        #pragma unroll
        for (int i = 0; i < 4; i++) CPA(sb + asw[i], agp[i] + ao);
        #pragma unroll
        for (int i = 0; i < 4; i++) CPA(sb + bsw[i], bgp[i] + bo);
        CP_COMMIT();
        if (1 < nIt) {
            offs(1, ao, bo);
            #pragma unroll
            for (int i = 0; i < 4; i++) CPA(sb + 32768u + asw[i], agp[i] + ao);
            #pragma unroll
            for (int i = 0; i < 4; i++) CPA(sb + 32768u + bsw[i], bgp[i] + bo);
        }
        CP_COMMIT();
    }

    int cur = 0;
    #pragma unroll 1
    for (int it = 0; it < nIt; ++it) {
        CP_WAIT1();
        __syncthreads();

        // issue stage it+2 first (buffer was released at this sync)
        if (it + 2 < nIt) {
            long ao, bo;
            offs(it + 2, ao, bo);
            int nst = cur + 2; if (nst >= 3) nst -= 3;
            uint32_t stg = (uint32_t)nst * 32768u;
            #pragma unroll
            for (int i = 0; i < 4; i++) CPA(sb + stg + asw[i], agp[i] + ao);
            #pragma unroll
            for (int i = 0; i < 4; i++) CPA(sb + stg + bsw[i], bgp[i] + bo);
        }
        CP_COMMIT();

        const uint32_t st = sb + (uint32_t)cur * 32768u;
        #pragma unroll
        for (int ks = 0; ks < 4; ks++) {
            const uint32_t kx = (uint32_t)(ks << 5);
            uint32_t bf[4][2];
            LDSM4(bf[0][0], bf[0][1], bf[1][0], bf[1][1], st + (bbase[0] ^ kx));
            LDSM4(bf[2][0], bf[2][1], bf[3][0], bf[3][1], st + (bbase[1] ^ kx));
            #pragma unroll
            for (int mi = 0; mi < 4; mi++) {
                uint32_t a0, a1, a2, a3;
                LDSM4(a0, a1, a2, a3, st + (abase[mi] ^ kx));
                #pragma unroll
                for (int nj = 0; nj < 4; nj++)
                    MMA16816(acc[mi][nj], a0, a1, a2, a3, bf[nj][0], bf[nj][1]);
            }
        }
        if (++cur == 3) cur = 0;
    }

    // ---------------- epilogue ----------------
    float* Cf = (float*)Cv + (long)blockIdx.z * sC;
    __nv_bfloat16* Cb = (__nv_bfloat16*)Cv + (long)blockIdx.z * sC;

    #pragma unroll
    for (int mi = 0; mi < 4; mi++) {
        const int m0 = bm + wm * 64 + mi * 16 + (lane >> 2);
        const int m1 = m0 + 8;
        const float bm0 = BIASM ? __ldg(&bias[m0]) : 0.f;
        const float bm1 = BIASM ? __ldg(&bias[m1]) : 0.f;
        float sc0 = 1.f, sc1 = 1.f;
        if (SCALEM) {
            sc0 = __ldg(&scalev[(long)blockIdx.z * LQ + m0]);
            sc1 = __ldg(&scalev[(long)blockIdx.z * LQ + m1]);
        }
        float s0 = 0.f, s1 = 0.f;
        #pragma unroll
        for (int nj = 0; nj < 4; nj++) {
            const int n = bn + wn * 32 + nj * 8 + (lane & 3) * 2;
            const float bn0 = BIASN ? __ldg(&bias[n])     : 0.f;
            const float bn1 = BIASN ? __ldg(&bias[n + 1]) : 0.f;
            float v00 = acc[mi][nj][0] + bm0 + bn0;
            float v01 = acc[mi][nj][1] + bm0 + bn1;
            float v10 = acc[mi][nj][2] + bm1 + bn0;
            float v11 = acc[mi][nj][3] + bm1 + bn1;
            if (SOFTEXP) {
                v00 = __expf(v00); v01 = __expf(v01);
                v10 = __expf(v10); v11 = __expf(v11);
                s0 += v00 + v01;
                s1 += v10 + v11;
            }
            if (SCALEM) { v00 *= sc0; v01 *= sc0; v10 *= sc1; v11 *= sc1; }
            if (POOLM) {
                float p00 = fmaxf(v00, __shfl_xor_sync(~0u, v00, 4));
                float p01 = fmaxf(v01, __shfl_xor_sync(~0u, v01, 4));
                float p10 = fmaxf(v10, __shfl_xor_sync(~0u, v10, 4));
                float p11 = fmaxf(v11, __shfl_xor_sync(~0u, v11, 4));
                if (!(lane & 4)) {
                    int pr0 = m0 >> 1, pr1 = m1 >> 1;
                    __nv_bfloat16 h0 = __float2bfloat16(p00), h1 = __float2bfloat16(p01);
                    __nv_bfloat16 h2 = __float2bfloat16(p10), h3 = __float2bfloat16(p11);
                    __nv_bfloat162 hh0; hh0.x = h0; hh0.y = h1;
                    __nv_bfloat162 hh1; hh1.x = h2; hh1.y = h3;
                    __nv_bfloat162 ll0;
                    ll0.x = __float2bfloat16(p00 - __bfloat162float(h0));
                    ll0.y = __float2bfloat16(p01 - __bfloat162float(h1));
                    __nv_bfloat162 ll1;
                    ll1.x = __float2bfloat16(p10 - __bfloat162float(h2));
                    ll1.y = __float2bfloat16(p11 - __bfloat162float(h3));
                    *(__nv_bfloat162*)&Cb[(long)pr0 * ldc + n] = hh0;
                    *(__nv_bfloat162*)&Cb[(long)pr0 * ldc + lo_off + n] = ll0;
                    *(__nv_bfloat162*)&Cb[(long)pr1 * ldc + n] = hh1;
                    *(__nv_bfloat162*)&Cb[(long)pr1 * ldc + lo_off + n] = ll1;
                }
            } else if (POOLN) {
                float p0 = fmaxf(v00, v01);
                float p1 = fmaxf(v10, v11);
                int np = n >> 1;
                __nv_bfloat16 h0 = __float2bfloat16(p0);
                __nv_bfloat16 h1 = __float2bfloat16(p1);
                Cb[(long)m0 * ldc + np] = h0;
                Cb[(long)m0 * ldc + lo_off + np] = __float2bfloat16(p0 - __bfloat162float(h0));
                Cb[(long)m1 * ldc + np] = h1;
                Cb[(long)m1 * ldc + lo_off + np] = __float2bfloat16(p1 - __bfloat162float(h1));
            } else if (SPLIT || SOFTEXP) {
                __nv_bfloat16 h00 = __float2bfloat16(v00), h01 = __float2bfloat16(v01);
                __nv_bfloat16 h10 = __float2bfloat16(v10), h11 = __float2bfloat16(v11);
                __nv_bfloat162 hh0; hh0.x = h00; hh0.y = h01;
                __nv_bfloat162 hh1; hh1.x = h10; hh1.y = h11;
                __nv_bfloat162 ll0;
                ll0.x = __float2bfloat16(v00 - __bfloat162float(h00));
                ll0.y = __float2bfloat16(v01 - __bfloat162float(h01));
                __nv_bfloat162 ll1;
                ll1.x = __float2bfloat16(v10 - __bfloat162float(h10));
                ll1.y = __float2bfloat16(v11 - __bfloat162float(h11));
                *(__nv_bfloat162*)&Cb[(long)m0 * ldc + n] = hh0;
                *(__nv_bfloat162*)&Cb[(long)m0 * ldc + lo_off + n] = ll0;
                *(__nv_bfloat162*)&Cb[(long)m1 * ldc + n] = hh1;
                *(__nv_bfloat162*)&Cb[(long)m1 * ldc + lo_off + n] = ll1;
            } else {
                *(float2*)&Cf[(long)m0 * ldc + n] = make_float2(v00, v01);
                *(float2*)&Cf[(long)m1 * ldc + n] = make_float2(v10, v11);
            }
        }
        if (SOFTEXP) {
            // sum the 4 lanes (lane&3) covering this warp's 32-col chunk
            s0 += __shfl_xor_sync(~0u, s0, 1);
            s0 += __shfl_xor_sync(~0u, s0, 2);
            s1 += __shfl_xor_sync(~0u, s1, 1);
            s1 += __shfl_xor_sync(~0u, s1, 2);
            if ((lane & 3) == 0) {
                long base = ((long)blockIdx.z * LQ + m0) * 64 + blockIdx.x * 4 + wn;
                psum[base] = s0;
                psum[base + 8 * 64] = s1;   // row m1 = m0+8
            }
        }
    }
}

// --------------------------------------------------------------- aux kernels
__device__ __forceinline__ void split_store(__nv_bfloat16* hi_p, __nv_bfloat16* lo_p, float v) {
    __nv_bfloat16 h = __float2bfloat16(v);
    *hi_p = h;
    *lo_p = __float2bfloat16(v - __bfloat162float(h));
}

__global__ __launch_bounds__(256)
void wsplit_all_kernel(const float* __restrict__ tw, const float* __restrict__ pw,
                       const float* __restrict__ gw, const float* __restrict__ zw,
                       __nv_bfloat16* __restrict__ ot, __nv_bfloat16* __restrict__ op,
                       __nv_bfloat16* __restrict__ og, __nv_bfloat16* __restrict__ oz)
{
    int i = blockIdx.x * 256 + threadIdx.x;
    int which = i >> 17;
    int j = i & 131071;
    const float* w; __nv_bfloat16* o; int Kc;
    if      (which == 0) { w = tw; o = ot; Kc = 512; }
    else if (which == 1) { w = pw; o = op; Kc = 512; }
    else if (which == 2) { w = gw; o = og; Kc = 512; }
    else                 { w = zw; o = oz; Kc = 256; }
    int r = j / Kc, k = j - r * Kc;
    split_store(&o[(long)r * 2 * Kc + k], &o[(long)r * 2 * Kc + Kc + k], w[j]);
}

__global__ __launch_bounds__(256)
void transpose_split_kernel(const float* __restrict__ x, __nv_bfloat16* __restrict__ xt)
{
    __shared__ float t[32][33];
    int b = blockIdx.z;
    int l0 = blockIdx.x * 32, c0 = blockIdx.y * 32;
    int tx = threadIdx.x & 31, ty = threadIdx.x >> 5;
    const float* px = x + ((long)b * CFULL + c0) * LQ + l0;
    #pragma unroll
    for (int i = 0; i < 32; i += 8) t[ty + i][tx] = px[(long)(ty + i) * LQ + tx];
    __syncthreads();
    __nv_bfloat16* po = xt + ((long)b * LQ + l0) * 1024 + c0;
    #pragma unroll
    for (int i = 0; i < 32; i += 8) {
        float v = t[tx][ty + i];
        split_store(&po[(long)(ty + i) * 1024 + tx],
                    &po[(long)(ty + i) * 1024 + 512 + tx], v);
    }
}

// reduce psum[row][64] -> inv[row] = 1/sum
__global__ __launch_bounds__(256)
void rowsum_inv_kernel(const float* __restrict__ psum, float* __restrict__ inv)
{
    int row = blockIdx.x * 8 + (threadIdx.x >> 5);
    int lane = threadIdx.x & 31;
    const float* p = psum + (long)row * 64;
    float s = p[lane] + p[lane + 32];
    #pragma unroll
    for (int o = 16; o; o >>= 1) s += __shfl_xor_sync(~0u, s, o);
    if (lane == 0) inv[row] = 1.f / s;
}

__global__ __launch_bounds__(256)
void bn_stats_kernel(const float* __restrict__ z, float* __restrict__ mean,
                     float* __restrict__ var)
{
    __shared__ float ss_s[8], ss_q[8];
    int c = blockIdx.x, tid = threadIdx.x, lane = tid & 31, warp = tid >> 5;
    float s = 0.f, q = 0.f;
    for (int b = 0; b < BATCH; b++) {
        const float* p = z + ((long)b * CFULL + c) * LQ;
        for (int l = tid * 4; l < LQ; l += 256 * 4) {
            float4 v = *(const float4*)&p[l];
            s += v.x + v.y + v.z + v.w;
            q += v.x * v.x + v.y * v.y + v.z * v.z + v.w * v.w;
        }
    }
    #pragma unroll
    for (int o = 16; o; o >>= 1) {
        s += __shfl_xor_sync(~0u, s, o);
        q += __shfl_xor_sync(~0u, q, o);
    }
    if (lane == 0) { ss_s[warp] = s; ss_q[warp] = q; }
    __syncthreads();
    if (tid == 0) {
        float S = 0.f, Q = 0.f;
        #pragma unroll
        for (int w = 0; w < 8; w++) { S += ss_s[w]; Q += ss_q[w]; }
        const float invN = 1.f / (float)(BATCH * LQ);
        float mu = S * invN;
        mean[c] = mu;
        var[c] = Q * invN - mu * mu;
    }
}

__global__ __launch_bounds__(256)
void bn_apply_kernel(const float* __restrict__ z, const float* __restrict__ x,
                     const float* __restrict__ gamma, const float* __restrict__ beta,
                     const float* __restrict__ mean, const float* __restrict__ var,
                     float* __restrict__ out)
{
    long base = ((long)blockIdx.x * 256 + threadIdx.x) * 4;
    int c = (int)((base >> 12) & (CFULL - 1));
    float scale = gamma[c] * rsqrtf(var[c] + 1e-5f);
    float shift = beta[c] - mean[c] * scale;
    float4 zv = *(const float4*)&z[base];
    float4 xv = *(const float4*)&x[base];
    float4 o;
    o.x = zv.x * scale + shift + xv.x;
    o.y = zv.y * scale + shift + xv.y;
    o.z = zv.z * scale + shift + xv.z;
    o.w = zv.w * scale + shift + xv.w;
    *(float4*)&out[base] = o;
}

// --------------------------------------------------------------- launch
extern "C" void kernel_launch(void* const* d_in, const int* in_sizes, int n_in,
                              void* d_out, int out_size)
{
    const float* x       = (const float*)d_in[0];
    const float* theta_w = (const float*)d_in[1];
    const float* theta_b = (const float*)d_in[2];
    const float* phi_w   = (const float*)d_in[3];
    const float* phi_b   = (const float*)d_in[4];
    const float* g_w     = (const float*)d_in[5];
    const float* g_b     = (const float*)d_in[6];
    const float* wz_w    = (const float*)d_in[7];
    const float* wz_b    = (const float*)d_in[8];
    const float* gamma   = (const float*)d_in[9];
    const float* beta    = (const float*)d_in[10];
    float* out = (float*)d_out;

    __nv_bfloat16 *xt, *thetaT, *phiPT, *gP, *fs, *yT, *wth, *wph, *wg, *wwz;
    float *psum, *inv, *z, *mean, *var;
    cudaGetSymbolAddress((void**)&xt,     g_xt);
    cudaGetSymbolAddress((void**)&thetaT, g_thetaT);
    cudaGetSymbolAddress((void**)&phiPT,  g_phiPT);
    cudaGetSymbolAddress((void**)&gP,     g_gP);
    cudaGetSymbolAddress((void**)&fs,     g_fs);
    cudaGetSymbolAddress((void**)&psum,   g_psum);
    cudaGetSymbolAddress((void**)&inv,    g_inv);
    cudaGetSymbolAddress((void**)&yT,     g_yT);
    cudaGetSymbolAddress((void**)&z,      g_z);
    cudaGetSymbolAddress((void**)&wth,    g_wth);
    cudaGetSymbolAddress((void**)&wph,    g_wph);
    cudaGetSymbolAddress((void**)&wg,     g_wg);
    cudaGetSymbolAddress((void**)&wwz,    g_wwz);
    cudaGetSymbolAddress((void**)&mean,   g_mean);
    cudaGetSymbolAddress((void**)&var,    g_var);

    cudaFuncSetAttribute((const void*)mma_gemm<0,1,1,0,0,0,0>, cudaFuncAttributeMaxDynamicSharedMemorySize, SM_BYTES);
    cudaFuncSetAttribute((const void*)mma_gemm<0,1,1,1,0,0,0>, cudaFuncAttributeMaxDynamicSharedMemorySize, SM_BYTES);
    cudaFuncSetAttribute((const void*)mma_gemm<1,0,1,0,1,0,0>, cudaFuncAttributeMaxDynamicSharedMemorySize, SM_BYTES);
    cudaFuncSetAttribute((const void*)mma_gemm<0,0,0,0,0,1,0>, cudaFuncAttributeMaxDynamicSharedMemorySize, SM_BYTES);
    cudaFuncSetAttribute((const void*)mma_gemm<0,0,1,0,0,0,1>, cudaFuncAttributeMaxDynamicSharedMemorySize, SM_BYTES);
    cudaFuncSetAttribute((const void*)mma_gemm<1,0,0,0,0,0,0>, cudaFuncAttributeMaxDynamicSharedMemorySize, SM_BYTES);

    dim3 blk(256);

    wsplit_all_kernel<<<2048, blk>>>(theta_w, phi_w, g_w, wz_w, wth, wph, wg, wwz);
    transpose_split_kernel<<<dim3(LQ / 32, CFULL / 32, BATCH), blk>>>(x, xt);

    // thetaT[L,Ci] split = xT * theta_w^T  (+bias n)
    mma_gemm<0,1,1,0,0,0,0><<<dim3(2, 32, BATCH), blk, SM_BYTES>>>(
        xt, wth, theta_b, nullptr, nullptr, thetaT, 512, 1024, 1024, 512, 256,
        (long)LQ * 1024, 0L, (long)LQ * 512);

    // phiP[L/2,Ci] split = maxpool_m(xT * phi_w^T + bias n)
    mma_gemm<0,1,1,1,0,0,0><<<dim3(2, 32, BATCH), blk, SM_BYTES>>>(
        xt, wph, phi_b, nullptr, nullptr, phiPT, 512, 1024, 1024, 512, 256,
        (long)LQ * 1024, 0L, (long)LK * 512);

    // gP[Ci,L/2] split = maxpool_n(g_w * xT^T + bias m)
    mma_gemm<1,0,1,0,1,0,0><<<dim3(32, 2, BATCH), blk, SM_BYTES>>>(
        wg, xt, g_b, nullptr, nullptr, gP, 512, 1024, 1024, 4096, 2048,
        0L, (long)LQ * 1024, (long)CI * 4096);

    // fs = exp(thetaT * phiP^T) split, plus partial row sums
    mma_gemm<0,0,0,0,0,1,0><<<dim3(16, 32, BATCH), blk, SM_BYTES>>>(
        thetaT, phiPT, nullptr, nullptr, psum, fs, 256, 512, 512, 4096, 2048,
        (long)LQ * 512, (long)LK * 512, (long)LQ * 4096);

    rowsum_inv_kernel<<<BATCH * LQ / 8, blk>>>(psum, inv);

    // yT[L,Ci] split = (fs * gP^T) * inv[row]
    mma_gemm<0,0,1,0,0,0,1><<<dim3(2, 32, BATCH), blk, SM_BYTES>>>(
        fs, gP, nullptr, inv, nullptr, yT, 2048, 4096, 4096, 512, 256,
        (long)LQ * 4096, (long)CI * 4096, (long)LQ * 512);

    // z[C,L] fp32 = wz_w * yT^T  (+bias m)
    mma_gemm<1,0,0,0,0,0,0><<<dim3(32, 4, BATCH), blk, SM_BYTES>>>(
        wwz, yT, wz_b, nullptr, nullptr, z, 256, 512, 512, LQ, 0,
        0L, (long)LQ * 512, (long)CFULL * LQ);

    bn_stats_kernel<<<CFULL, blk>>>(z, mean, var);
    bn_apply_kernel<<<(BATCH * CFULL * LQ) / (256 * 4), blk>>>(
        z, x, gamma, beta, mean, var, out);
}

// round 8
// speedup vs baseline: 2.9327x; 1.0268x over previous
#include <cuda_runtime.h>
#include <cuda_bf16.h>
#include <cstdint>

#define BATCH 8
#define CFULL 512
#define CI    256
#define LQ    4096
#define LK    2048

#define SWZ(x) ((x) ^ (((x) >> 3) & 0x70))

__device__ __forceinline__ uint32_t smem_u32(const void* p) {
    uint32_t a;
    asm("{ .reg .u64 t; cvta.to.shared.u64 t, %1; cvt.u32.u64 %0, t; }" : "=r"(a) : "l"(p));
    return a;
}

#define CPA(saddr, gptr) \
    asm volatile("cp.async.cg.shared.global [%0], [%1], 16;" :: "r"(saddr), "l"(gptr))
#define CP_COMMIT() asm volatile("cp.async.commit_group;" ::: "memory")
#define CP_WAIT1()  asm volatile("cp.async.wait_group 1;" ::: "memory")

#define LDSM4(r0, r1, r2, r3, addr) \
    asm volatile("ldmatrix.sync.aligned.m8n8.x4.shared.b16 {%0,%1,%2,%3}, [%4];" \
        : "=r"(r0), "=r"(r1), "=r"(r2), "=r"(r3) : "r"(addr))

#define MMA16816(d, a0, a1, a2, a3, b0, b1) \
    asm volatile("mma.sync.aligned.m16n8k16.row.col.f32.bf16.bf16.f32 " \
        "{%0,%1,%2,%3}, {%4,%5,%6,%7}, {%8,%9}, {%0,%1,%2,%3};" \
        : "+f"((d)[0]), "+f"((d)[1]), "+f"((d)[2]), "+f"((d)[3]) \
        : "r"(a0), "r"(a1), "r"(a2), "r"(a3), "r"(b0), "r"(b1))

// --------------------------------------------------------------- scratch
__device__ __nv_bfloat16 g_xt    [(size_t)BATCH * LQ * 1024];     // xT split [B][L][2C]
__device__ __nv_bfloat16 g_thetaT[(size_t)BATCH * LQ * 512];      // [B][L][2Ci]
__device__ __nv_bfloat16 g_phiPT [(size_t)BATCH * LK * 512];      // [B][L/2][2Ci]
__device__ __nv_bfloat16 g_gP    [(size_t)BATCH * CI * 4096];     // [B][Ci][2*L/2] split
__device__ __nv_bfloat16 g_fs    [(size_t)BATCH * LQ * 4096];     // exp(f) split
__device__ float         g_psum  [(size_t)BATCH * LQ * 32];       // partial row sums
__device__ float         g_inv   [(size_t)BATCH * LQ];            // 1/rowsum
__device__ __nv_bfloat16 g_yT    [(size_t)BATCH * LQ * 512];      // [B][L][2Ci]
__device__ float         g_z     [(size_t)BATCH * CFULL * LQ];    // [B][C][L]
__device__ float         g_bns   [(size_t)CFULL * 512];           // BN partial sums
__device__ float         g_bnq   [(size_t)CFULL * 512];           // BN partial sumsq
__device__ __nv_bfloat16 g_wth   [CI * 1024];
__device__ __nv_bfloat16 g_wph   [CI * 1024];
__device__ __nv_bfloat16 g_wg    [CI * 1024];
__device__ __nv_bfloat16 g_wwz   [CFULL * 512];
__device__ float g_mean[CFULL];
__device__ float g_var [CFULL];

// --------------------------------------------------------------- HMMA GEMM
// D[M,N] = sum over 3 split terms of A*B^T: (Ahi,Bhi),(Ahi,Blo),(Alo,Bhi).
// CTA tile 128x128, 128 threads, 4 warps (2m x 2n), warp tile 64x64,
// BK=64, 3-stage cp.async.
#define SM_BYTES 98304
template<int BIASM, int BIASN, int SPLIT, int POOLM, int POOLN, int SOFTEXP, int SCALEM,
         int BNSTAT>
__global__ __launch_bounds__(128, 2)
void mma_gemm(const __nv_bfloat16* __restrict__ A, const __nv_bfloat16* __restrict__ B,
              const float* __restrict__ bias, const float* __restrict__ scalev,
              float* __restrict__ psum, float* __restrict__ psumq,
              void* __restrict__ Cv,
              int K, int lda, int ldb, int ldc, int lo_off,
              long sA, long sB, long sC)
{
    extern __shared__ char smem[];
    const uint32_t sb = smem_u32(smem);
    const int tid = threadIdx.x;
    const int wid = tid >> 5;
    const int lane = tid & 31;
    const int bm = blockIdx.y * 128;
    const int bn = blockIdx.x * 128;
    A += (long)blockIdx.z * sA;
    B += (long)blockIdx.z * sB;

    // loader: thread covers rows r0, r0+16, ..., r0+112 at col chunk c (16B)
    const int r0 = tid >> 3;
    const int c0 = tid & 7;
    const __nv_bfloat16* agp0 = A + (long)(bm + r0) * lda + c0 * 8;
    const __nv_bfloat16* bgp0 = B + (long)(bn + r0) * ldb + c0 * 8;
    const uint32_t asw0 = SWZ((uint32_t)(r0 * 128 + c0 * 16));          // +i*2048
    const long astep = 16L * lda;
    const long bstep = 16L * ldb;

    const int wm = wid >> 1;        // 0..1
    const int wn = wid & 1;         // 0..1
    uint32_t abase[4], bbase[4];
    #pragma unroll
    for (int mi = 0; mi < 4; mi++) {
        int arow = wm * 64 + mi * 16 + (lane & 15);
        abase[mi] = (uint32_t)(arow * 128) + ((((lane >> 4) << 4)) ^ ((arow & 7) << 4));
    }
    #pragma unroll
    for (int j2 = 0; j2 < 4; j2++) {
        int brow = wn * 64 + j2 * 16 + (lane & 7) + ((lane >> 4) << 3);
        uint32_t bcol = ((lane >> 3) & 1) << 4;
        bbase[j2] = 16384u + (uint32_t)(brow * 128) + (bcol ^ ((brow & 7) << 4));
    }

    float acc[4][8][4];
    #pragma unroll
    for (int i = 0; i < 4; i++)
        #pragma unroll
        for (int j = 0; j < 8; j++)
            #pragma unroll
            for (int q = 0; q < 4; q++)
                acc[i][j][q] = 0.f;

    const int kper = K >> 6;
    const int nIt = 3 * kper;

    auto offs = [&](int n, long& ao, long& bo) {
        int term = n / kper;
        int kk = (n - term * kper) << 6;
        ao = ((term == 2) ? (long)K : 0L) + kk;
        bo = ((term == 1) ? (long)K : 0L) + kk;
    };

    {   // prologue: stages 0 and 1
        long ao, bo;
        offs(0, ao, bo);
        #pragma unroll
        for (int i = 0; i < 8; i++) CPA(sb + asw0 + i * 2048u, agp0 + ao + i * astep);
        #pragma unroll
        for (int i = 0; i < 8; i++) CPA(sb + 16384u + asw0 + i * 2048u, bgp0 + bo + i * bstep);
        CP_COMMIT();
        if (1 < nIt) {
            offs(1, ao, bo);
            #pragma unroll
            for (int i = 0; i < 8; i++) CPA(sb + 32768u + asw0 + i * 2048u, agp0 + ao + i * astep);
            #pragma unroll
            for (int i = 0; i < 8; i++) CPA(sb + 49152u + asw0 + i * 2048u, bgp0 + bo + i * bstep);
        }
        CP_COMMIT();
    }

    int cur = 0;
    #pragma unroll 1
    for (int it = 0; it < nIt; ++it) {
        CP_WAIT1();
        __syncthreads();

        if (it + 2 < nIt) {
            long ao, bo;
            offs(it + 2, ao, bo);
            int nst = cur + 2; if (nst >= 3) nst -= 3;
            uint32_t stg = (uint32_t)nst * 32768u;
            #pragma unroll
            for (int i = 0; i < 8; i++) CPA(sb + stg + asw0 + i * 2048u, agp0 + ao + i * astep);
            #pragma unroll
            for (int i = 0; i < 8; i++) CPA(sb + stg + 16384u + asw0 + i * 2048u, bgp0 + bo + i * bstep);
        }
        CP_COMMIT();

        const uint32_t st = sb + (uint32_t)cur * 32768u;
        #pragma unroll
        for (int ks = 0; ks < 4; ks++) {
            const uint32_t kx = (uint32_t)(ks << 5);
            uint32_t bf[8][2];
            LDSM4(bf[0][0], bf[0][1], bf[1][0], bf[1][1], st + (bbase[0] ^ kx));
            LDSM4(bf[2][0], bf[2][1], bf[3][0], bf[3][1], st + (bbase[1] ^ kx));
            LDSM4(bf[4][0], bf[4][1], bf[5][0], bf[5][1], st + (bbase[2] ^ kx));
            LDSM4(bf[6][0], bf[6][1], bf[7][0], bf[7][1], st + (bbase[3] ^ kx));
            #pragma unroll
            for (int mi = 0; mi < 4; mi++) {
                uint32_t a0, a1, a2, a3;
                LDSM4(a0, a1, a2, a3, st + (abase[mi] ^ kx));
                #pragma unroll
                for (int nj = 0; nj < 8; nj++)
                    MMA16816(acc[mi][nj], a0, a1, a2, a3, bf[nj][0], bf[nj][1]);
            }
        }
        if (++cur == 3) cur = 0;
    }

    // ---------------- epilogue ----------------
    float* Cf = (float*)Cv + (long)blockIdx.z * sC;
    __nv_bfloat16* Cb = (__nv_bfloat16*)Cv + (long)blockIdx.z * sC;

    #pragma unroll
    for (int mi = 0; mi < 4; mi++) {
        const int m0 = bm + wm * 64 + mi * 16 + (lane >> 2);
        const int m1 = m0 + 8;
        const float bm0 = BIASM ? __ldg(&bias[m0]) : 0.f;
        const float bm1 = BIASM ? __ldg(&bias[m1]) : 0.f;
        float sc0 = 1.f, sc1 = 1.f;
        if (SCALEM) {
            sc0 = __ldg(&scalev[(long)blockIdx.z * LQ + m0]);
            sc1 = __ldg(&scalev[(long)blockIdx.z * LQ + m1]);
        }
        float s0 = 0.f, s1 = 0.f, q0 = 0.f, q1 = 0.f;
        #pragma unroll
        for (int nj = 0; nj < 8; nj++) {
            const int n = bn + wn * 64 + nj * 8 + (lane & 3) * 2;
            const float bn0 = BIASN ? __ldg(&bias[n])     : 0.f;
            const float bn1 = BIASN ? __ldg(&bias[n + 1]) : 0.f;
            float v00 = acc[mi][nj][0] + bm0 + bn0;
            float v01 = acc[mi][nj][1] + bm0 + bn1;
            float v10 = acc[mi][nj][2] + bm1 + bn0;
            float v11 = acc[mi][nj][3] + bm1 + bn1;
            if (SOFTEXP) {
                v00 = __expf(v00); v01 = __expf(v01);
                v10 = __expf(v10); v11 = __expf(v11);
                s0 += v00 + v01;
                s1 += v10 + v11;
            }
            if (BNSTAT) {
                s0 += v00 + v01; s1 += v10 + v11;
                q0 += v00 * v00 + v01 * v01;
                q1 += v10 * v10 + v11 * v11;
            }
            if (SCALEM) { v00 *= sc0; v01 *= sc0; v10 *= sc1; v11 *= sc1; }
            if (POOLM) {
                float p00 = fmaxf(v00, __shfl_xor_sync(~0u, v00, 4));
                float p01 = fmaxf(v01, __shfl_xor_sync(~0u, v01, 4));
                float p10 = fmaxf(v10, __shfl_xor_sync(~0u, v10, 4));
                float p11 = fmaxf(v11, __shfl_xor_sync(~0u, v11, 4));
                if (!(lane & 4)) {
                    int pr0 = m0 >> 1, pr1 = m1 >> 1;
                    __nv_bfloat16 h0 = __float2bfloat16(p00), h1 = __float2bfloat16(p01);
                    __nv_bfloat16 h2 = __float2bfloat16(p10), h3 = __float2bfloat16(p11);
                    __nv_bfloat162 hh0; hh0.x = h0; hh0.y = h1;
                    __nv_bfloat162 hh1; hh1.x = h2; hh1.y = h3;
                    __nv_bfloat162 ll0;
                    ll0.x = __float2bfloat16(p00 - __bfloat162float(h0));
                    ll0.y = __float2bfloat16(p01 - __bfloat162float(h1));
                    __nv_bfloat162 ll1;
                    ll1.x = __float2bfloat16(p10 - __bfloat162float(h2));
                    ll1.y = __float2bfloat16(p11 - __bfloat162float(h3));
                    *(__nv_bfloat162*)&Cb[(long)pr0 * ldc + n] = hh0;
                    *(__nv_bfloat162*)&Cb[(long)pr0 * ldc + lo_off + n] = ll0;
                    *(__nv_bfloat162*)&Cb[(long)pr1 * ldc + n] = hh1;
                    *(__nv_bfloat162*)&Cb[(long)pr1 * ldc + lo_off + n] = ll1;
                }
            } else if (POOLN) {
                float p0 = fmaxf(v00, v01);
                float p1 = fmaxf(v10, v11);
                int np = n >> 1;
                __nv_bfloat16 h0 = __float2bfloat16(p0);
                __nv_bfloat16 h1 = __float2bfloat16(p1);
                Cb[(long)m0 * ldc + np] = h0;
                Cb[(long)m0 * ldc + lo_off + np] = __float2bfloat16(p0 - __bfloat162float(h0));
                Cb[(long)m1 * ldc + np] = h1;
                Cb[(long)m1 * ldc + lo_off + np] = __float2bfloat16(p1 - __bfloat162float(h1));
            } else if (SPLIT || SOFTEXP) {
                __nv_bfloat16 h00 = __float2bfloat16(v00), h01 = __float2bfloat16(v01);
                __nv_bfloat16 h10 = __float2bfloat16(v10), h11 = __float2bfloat16(v11);
                __nv_bfloat162 hh0; hh0.x = h00; hh0.y = h01;
                __nv_bfloat162 hh1; hh1.x = h10; hh1.y = h11;
                __nv_bfloat162 ll0;
                ll0.x = __float2bfloat16(v00 - __bfloat162float(h00));
                ll0.y = __float2bfloat16(v01 - __bfloat162float(h01));
                __nv_bfloat162 ll1;
                ll1.x = __float2bfloat16(v10 - __bfloat162float(h10));
                ll1.y = __float2bfloat16(v11 - __bfloat162float(h11));
                *(__nv_bfloat162*)&Cb[(long)m0 * ldc + n] = hh0;
                *(__nv_bfloat162*)&Cb[(long)m0 * ldc + lo_off + n] = ll0;
                *(__nv_bfloat162*)&Cb[(long)m1 * ldc + n] = hh1;
                *(__nv_bfloat162*)&Cb[(long)m1 * ldc + lo_off + n] = ll1;
            } else {
                *(float2*)&Cf[(long)m0 * ldc + n] = make_float2(v00, v01);
                *(float2*)&Cf[(long)m1 * ldc + n] = make_float2(v10, v11);
            }
        }
        if (SOFTEXP) {
            s0 += __shfl_xor_sync(~0u, s0, 1);
            s0 += __shfl_xor_sync(~0u, s0, 2);
            s1 += __shfl_xor_sync(~0u, s1, 1);
            s1 += __shfl_xor_sync(~0u, s1, 2);
            if ((lane & 3) == 0) {
                long base = ((long)blockIdx.z * LQ + m0) * 32 + blockIdx.x * 2 + wn;
                psum[base] = s0;
                psum[base + 8 * 32] = s1;
            }
        }
        if (BNSTAT) {
            s0 += __shfl_xor_sync(~0u, s0, 1);
            s0 += __shfl_xor_sync(~0u, s0, 2);
            s1 += __shfl_xor_sync(~0u, s1, 1);
            s1 += __shfl_xor_sync(~0u, s1, 2);
            q0 += __shfl_xor_sync(~0u, q0, 1);
            q0 += __shfl_xor_sync(~0u, q0, 2);
            q1 += __shfl_xor_sync(~0u, q1, 1);
            q1 += __shfl_xor_sync(~0u, q1, 2);
            if ((lane & 3) == 0) {
                int col = blockIdx.z * 64 + blockIdx.x * 2 + wn;
                psum [(long)m0 * 512 + col] = s0;
                psum [(long)m1 * 512 + col] = s1;
                psumq[(long)m0 * 512 + col] = q0;
                psumq[(long)m1 * 512 + col] = q1;
            }
        }
    }
}

// --------------------------------------------------------------- aux kernels
__device__ __forceinline__ void split_store(__nv_bfloat16* hi_p, __nv_bfloat16* lo_p, float v) {
    __nv_bfloat16 h = __float2bfloat16(v);
    *hi_p = h;
    *lo_p = __float2bfloat16(v - __bfloat162float(h));
}

__global__ __launch_bounds__(256)
void wsplit_all_kernel(const float* __restrict__ tw, const float* __restrict__ pw,
                       const float* __restrict__ gw, const float* __restrict__ zw,
                       __nv_bfloat16* __restrict__ ot, __nv_bfloat16* __restrict__ op,
                       __nv_bfloat16* __restrict__ og, __nv_bfloat16* __restrict__ oz)
{
    int i = blockIdx.x * 256 + threadIdx.x;
    int which = i >> 17;
    int j = i & 131071;
    const float* w; __nv_bfloat16* o; int Kc;
    if      (which == 0) { w = tw; o = ot; Kc = 512; }
    else if (which == 1) { w = pw; o = op; Kc = 512; }
    else if (which == 2) { w = gw; o = og; Kc = 512; }
    else                 { w = zw; o = oz; Kc = 256; }
    int r = j / Kc, k = j - r * Kc;
    split_store(&o[(long)r * 2 * Kc + k], &o[(long)r * 2 * Kc + Kc + k], w[j]);
}

__global__ __launch_bounds__(256)
void transpose_split_kernel(const float* __restrict__ x, __nv_bfloat16* __restrict__ xt)
{
    __shared__ float t[32][33];
    int b = blockIdx.z;
    int l0 = blockIdx.x * 32, c0 = blockIdx.y * 32;
    int tx = threadIdx.x & 31, ty = threadIdx.x >> 5;
    const float* px = x + ((long)b * CFULL + c0) * LQ + l0;
    #pragma unroll
    for (int i = 0; i < 32; i += 8) t[ty + i][tx] = px[(long)(ty + i) * LQ + tx];
    __syncthreads();
    __nv_bfloat16* po = xt + ((long)b * LQ + l0) * 1024 + c0;
    #pragma unroll
    for (int i = 0; i < 32; i += 8) {
        float v = t[tx][ty + i];
        split_store(&po[(long)(ty + i) * 1024 + tx],
                    &po[(long)(ty + i) * 1024 + 512 + tx], v);
    }
}

__global__ __launch_bounds__(256)
void rowsum_inv_kernel(const float* __restrict__ psum, float* __restrict__ inv)
{
    int row = blockIdx.x * 8 + (threadIdx.x >> 5);
    int lane = threadIdx.x & 31;
    float s = psum[(long)row * 32 + lane];
    #pragma unroll
    for (int o = 16; o; o >>= 1) s += __shfl_xor_sync(~0u, s, o);
    if (lane == 0) inv[row] = 1.f / s;
}

__global__ __launch_bounds__(256)
void bn_reduce_kernel(const float* __restrict__ bns, const float* __restrict__ bnq,
                      float* __restrict__ mean, float* __restrict__ var)
{
    __shared__ float ss_s[8], ss_q[8];
    int c = blockIdx.x, tid = threadIdx.x, lane = tid & 31, warp = tid >> 5;
    float s = 0.f, q = 0.f;
    #pragma unroll
    for (int i = 0; i < 2; i++) {
        s += bns[(long)c * 512 + tid + i * 256];
        q += bnq[(long)c * 512 + tid + i * 256];
    }
    #pragma unroll
    for (int o = 16; o; o >>= 1) {
        s += __shfl_xor_sync(~0u, s, o);
        q += __shfl_xor_sync(~0u, q, o);
    }
    if (lane == 0) { ss_s[warp] = s; ss_q[warp] = q; }
    __syncthreads();
    if (tid == 0) {
        float S = 0.f, Q = 0.f;
        #pragma unroll
        for (int w = 0; w < 8; w++) { S += ss_s[w]; Q += ss_q[w]; }
        const float invN = 1.f / (float)(BATCH * LQ);
        float mu = S * invN;
        mean[c] = mu;
        var[c] = Q * invN - mu * mu;
    }
}

__global__ __launch_bounds__(256)
void bn_apply_kernel(const float* __restrict__ z, const float* __restrict__ x,
                     const float* __restrict__ gamma, const float* __restrict__ beta,
                     const float* __restrict__ mean, const float* __restrict__ var,
                     float* __restrict__ out)
{
    long base = ((long)blockIdx.x * 256 + threadIdx.x) * 4;
    int c = (int)((base >> 12) & (CFULL - 1));
    float scale = gamma[c] * rsqrtf(var[c] + 1e-5f);
    float shift = beta[c] - mean[c] * scale;
    float4 zv = *(const float4*)&z[base];
    float4 xv = *(const float4*)&x[base];
    float4 o;
    o.x = zv.x * scale + shift + xv.x;
    o.y = zv.y * scale + shift + xv.y;
    o.z = zv.z * scale + shift + xv.z;
    o.w = zv.w * scale + shift + xv.w;
    *(float4*)&out[base] = o;
}

// --------------------------------------------------------------- launch
extern "C" void kernel_launch(void* const* d_in, const int* in_sizes, int n_in,
                              void* d_out, int out_size)
{
    const float* x       = (const float*)d_in[0];
    const float* theta_w = (const float*)d_in[1];
    const float* theta_b = (const float*)d_in[2];
    const float* phi_w   = (const float*)d_in[3];
    const float* phi_b   = (const float*)d_in[4];
    const float* g_w     = (const float*)d_in[5];
    const float* g_b     = (const float*)d_in[6];
    const float* wz_w    = (const float*)d_in[7];
    const float* wz_b    = (const float*)d_in[8];
    const float* gamma   = (const float*)d_in[9];
    const float* beta    = (const float*)d_in[10];
    float* out = (float*)d_out;

    __nv_bfloat16 *xt, *thetaT, *phiPT, *gP, *fs, *yT, *wth, *wph, *wg, *wwz;
    float *psum, *inv, *z, *bns, *bnq, *mean, *var;
    cudaGetSymbolAddress((void**)&xt,     g_xt);
    cudaGetSymbolAddress((void**)&thetaT, g_thetaT);
    cudaGetSymbolAddress((void**)&phiPT,  g_phiPT);
    cudaGetSymbolAddress((void**)&gP,     g_gP);
    cudaGetSymbolAddress((void**)&fs,     g_fs);
    cudaGetSymbolAddress((void**)&psum,   g_psum);
    cudaGetSymbolAddress((void**)&inv,    g_inv);
    cudaGetSymbolAddress((void**)&yT,     g_yT);
    cudaGetSymbolAddress((void**)&z,      g_z);
    cudaGetSymbolAddress((void**)&bns,    g_bns);
    cudaGetSymbolAddress((void**)&bnq,    g_bnq);
    cudaGetSymbolAddress((void**)&wth,    g_wth);
    cudaGetSymbolAddress((void**)&wph,    g_wph);
    cudaGetSymbolAddress((void**)&wg,     g_wg);
    cudaGetSymbolAddress((void**)&wwz,    g_wwz);
    cudaGetSymbolAddress((void**)&mean,   g_mean);
    cudaGetSymbolAddress((void**)&var,    g_var);

    cudaFuncSetAttribute((const void*)mma_gemm<0,1,1,0,0,0,0,0>, cudaFuncAttributeMaxDynamicSharedMemorySize, SM_BYTES);
    cudaFuncSetAttribute((const void*)mma_gemm<0,1,1,1,0,0,0,0>, cudaFuncAttributeMaxDynamicSharedMemorySize, SM_BYTES);
    cudaFuncSetAttribute((const void*)mma_gemm<1,0,1,0,1,0,0,0>, cudaFuncAttributeMaxDynamicSharedMemorySize, SM_BYTES);
    cudaFuncSetAttribute((const void*)mma_gemm<0,0,0,0,0,1,0,0>, cudaFuncAttributeMaxDynamicSharedMemorySize, SM_BYTES);
    cudaFuncSetAttribute((const void*)mma_gemm<0,0,1,0,0,0,1,0>, cudaFuncAttributeMaxDynamicSharedMemorySize, SM_BYTES);
    cudaFuncSetAttribute((const void*)mma_gemm<1,0,0,0,0,0,0,1>, cudaFuncAttributeMaxDynamicSharedMemorySize, SM_BYTES);

    dim3 blk(256);
    dim3 mblk(128);

    wsplit_all_kernel<<<2048, blk>>>(theta_w, phi_w, g_w, wz_w, wth, wph, wg, wwz);
    transpose_split_kernel<<<dim3(LQ / 32, CFULL / 32, BATCH), blk>>>(x, xt);

    // thetaT[L,Ci] split = xT * theta_w^T  (+bias n)
    mma_gemm<0,1,1,0,0,0,0,0><<<dim3(2, 32, BATCH), mblk, SM_BYTES>>>(
        xt, wth, theta_b, nullptr, nullptr, nullptr, thetaT, 512, 1024, 1024, 512, 256,
        (long)LQ * 1024, 0L, (long)LQ * 512);

    // phiP[L/2,Ci] split = maxpool_m(xT * phi_w^T + bias n)
    mma_gemm<0,1,1,1,0,0,0,0><<<dim3(2, 32, BATCH), mblk, SM_BYTES>>>(
        xt, wph, phi_b, nullptr, nullptr, nullptr, phiPT, 512, 1024, 1024, 512, 256,
        (long)LQ * 1024, 0L, (long)LK * 512);

    // gP[Ci,L/2] split = maxpool_n(g_w * xT^T + bias m)
    mma_gemm<1,0,1,0,1,0,0,0><<<dim3(32, 2, BATCH), mblk, SM_BYTES>>>(
        wg, xt, g_b, nullptr, nullptr, nullptr, gP, 512, 1024, 1024, 4096, 2048,
        0L, (long)LQ * 1024, (long)CI * 4096);

    // fs = exp(thetaT * phiP^T) split bf16, plus partial row sums
    mma_gemm<0,0,0,0,0,1,0,0><<<dim3(16, 32, BATCH), mblk, SM_BYTES>>>(
        thetaT, phiPT, nullptr, nullptr, psum, nullptr, fs, 256, 512, 512, 4096, 2048,
        (long)LQ * 512, (long)LK * 512, (long)LQ * 4096);

    rowsum_inv_kernel<<<BATCH * LQ / 8, blk>>>(psum, inv);

    // yT[L,Ci] split = (fs_split * gP_split^T) * inv[row]  (3 terms)
    mma_gemm<0,0,1,0,0,0,1,0><<<dim3(2, 32, BATCH), mblk, SM_BYTES>>>(
        fs, gP, nullptr, inv, nullptr, nullptr, yT, 2048, 4096, 4096, 512, 256,
        (long)LQ * 4096, (long)CI * 4096, (long)LQ * 512);

    // z[C,L] fp32 = wz_w * yT^T  (+bias m), with fused BN partial stats
    mma_gemm<1,0,0,0,0,0,0,1><<<dim3(32, 4, BATCH), mblk, SM_BYTES>>>(
        wwz, yT, wz_b, nullptr, bns, bnq, z, 256, 512, 512, LQ, 0,
        0L, (long)LQ * 512, (long)CFULL * LQ);

    bn_reduce_kernel<<<CFULL, blk>>>(bns, bnq, mean, var);
    bn_apply_kernel<<<(BATCH * CFULL * LQ) / (256 * 4), blk>>>(
        z, x, gamma, beta, mean, var, out);
}

// round 9
// speedup vs baseline: 3.1413x; 1.0711x over previous
#include <cuda_runtime.h>
#include <cuda_bf16.h>
#include <cstdint>

#define BATCH 8
#define CFULL 512
#define CI    256
#define LQ    4096
#define LK    2048

#define SWZ(x) ((x) ^ (((x) >> 3) & 0x70))

__device__ __forceinline__ uint32_t smem_u32(const void* p) {
    uint32_t a;
    asm("{ .reg .u64 t; cvta.to.shared.u64 t, %1; cvt.u32.u64 %0, t; }" : "=r"(a) : "l"(p));
    return a;
}

#define CPA(saddr, gptr) \
    asm volatile("cp.async.cg.shared.global [%0], [%1], 16;" :: "r"(saddr), "l"(gptr))
#define CP_COMMIT() asm volatile("cp.async.commit_group;" ::: "memory")
#define CP_WAIT1()  asm volatile("cp.async.wait_group 1;" ::: "memory")

#define LDSM4(r0, r1, r2, r3, addr) \
    asm volatile("ldmatrix.sync.aligned.m8n8.x4.shared.b16 {%0,%1,%2,%3}, [%4];" \
        : "=r"(r0), "=r"(r1), "=r"(r2), "=r"(r3) : "r"(addr))

#define MMA16816(d, a0, a1, a2, a3, b0, b1) \
    asm volatile("mma.sync.aligned.m16n8k16.row.col.f32.bf16.bf16.f32 " \
        "{%0,%1,%2,%3}, {%4,%5,%6,%7}, {%8,%9}, {%0,%1,%2,%3};" \
        : "+f"((d)[0]), "+f"((d)[1]), "+f"((d)[2]), "+f"((d)[3]) \
        : "r"(a0), "r"(a1), "r"(a2), "r"(a3), "r"(b0), "r"(b1))

// --------------------------------------------------------------- scratch
__device__ __nv_bfloat16 g_xt    [(size_t)BATCH * LQ * 1024];     // xT split [B][L][2C]
__device__ __nv_bfloat16 g_thetaT[(size_t)BATCH * LQ * 512];      // [B][L][2Ci]
__device__ __nv_bfloat16 g_phiPT [(size_t)BATCH * LK * 512];      // [B][L/2][2Ci]
__device__ __nv_bfloat16 g_gP    [(size_t)BATCH * CI * 4096];     // [B][Ci][2*L/2] split
__device__ __nv_bfloat16 g_fs    [(size_t)BATCH * LQ * 4096];     // exp(f) split
__device__ float         g_psum  [(size_t)BATCH * LQ * 32];       // partial row sums
__device__ float         g_inv   [(size_t)BATCH * LQ];            // 1/rowsum
__device__ __nv_bfloat16 g_yT    [(size_t)BATCH * LQ * 512];      // [B][L][2Ci]
__device__ float         g_z     [(size_t)BATCH * CFULL * LQ];    // [B][C][L]
__device__ float         g_bns   [(size_t)CFULL * 512];           // BN partial sums
__device__ float         g_bnq   [(size_t)CFULL * 512];           // BN partial sumsq
__device__ __nv_bfloat16 g_wth   [CI * 1024];
__device__ __nv_bfloat16 g_wph   [CI * 1024];
__device__ __nv_bfloat16 g_wg    [CI * 1024];
__device__ __nv_bfloat16 g_wwz   [CFULL * 512];
__device__ float g_mean[CFULL];
__device__ float g_var [CFULL];

// --------------------------------------------------------------- HMMA GEMM
// D[M,N] = sum over 3 split terms of A*B^T: (Ahi,Bhi),(Ahi,Blo),(Alo,Bhi).
// CTA tile 128x128, 128 threads, 4 warps (2m x 2n), warp tile 64x64,
// BK=64, 3-stage cp.async, register-double-buffered fragments.
#define SM_BYTES 98304
template<int BIASM, int BIASN, int SPLIT, int POOLM, int POOLN, int SOFTEXP, int SCALEM,
         int BNSTAT>
__global__ __launch_bounds__(128, 2)
void mma_gemm(const __nv_bfloat16* __restrict__ A, const __nv_bfloat16* __restrict__ B,
              const float* __restrict__ bias, const float* __restrict__ scalev,
              float* __restrict__ psum, float* __restrict__ psumq,
              void* __restrict__ Cv,
              int K, int lda, int ldb, int ldc, int lo_off,
              long sA, long sB, long sC)
{
    extern __shared__ char smem[];
    const uint32_t sb = smem_u32(smem);
    const int tid = threadIdx.x;
    const int wid = tid >> 5;
    const int lane = tid & 31;
    const int bm = blockIdx.y * 128;
    const int bn = blockIdx.x * 128;
    A += (long)blockIdx.z * sA;
    B += (long)blockIdx.z * sB;

    // loader: thread covers rows r0, r0+16, ..., r0+112 at col chunk c0 (16B)
    const int r0 = tid >> 3;
    const int c0 = tid & 7;
    const __nv_bfloat16* agp0 = A + (long)(bm + r0) * lda + c0 * 8;
    const __nv_bfloat16* bgp0 = B + (long)(bn + r0) * ldb + c0 * 8;
    const uint32_t asw0 = SWZ((uint32_t)(r0 * 128 + c0 * 16));          // +i*2048
    const long astep = 16L * lda;
    const long bstep = 16L * ldb;

    const int wm = wid >> 1;        // 0..1
    const int wn = wid & 1;         // 0..1
    uint32_t abase[4], bbase[4];
    #pragma unroll
    for (int mi = 0; mi < 4; mi++) {
        int arow = wm * 64 + mi * 16 + (lane & 15);
        abase[mi] = (uint32_t)(arow * 128) + ((((lane >> 4) << 4)) ^ ((arow & 7) << 4));
    }
    #pragma unroll
    for (int j2 = 0; j2 < 4; j2++) {
        int brow = wn * 64 + j2 * 16 + (lane & 7) + ((lane >> 4) << 3);
        uint32_t bcol = ((lane >> 3) & 1) << 4;
        bbase[j2] = 16384u + (uint32_t)(brow * 128) + (bcol ^ ((brow & 7) << 4));
    }

    float acc[4][8][4];
    #pragma unroll
    for (int i = 0; i < 4; i++)
        #pragma unroll
        for (int j = 0; j < 8; j++)
            #pragma unroll
            for (int q = 0; q < 4; q++)
                acc[i][j][q] = 0.f;

    const int kper = K >> 6;
    const int nIt = 3 * kper;

    auto offs = [&](int n, long& ao, long& bo) {
        int term = n / kper;
        int kk = (n - term * kper) << 6;
        ao = ((term == 2) ? (long)K : 0L) + kk;
        bo = ((term == 1) ? (long)K : 0L) + kk;
    };

    {   // prologue: stages 0 and 1
        long ao, bo;
        offs(0, ao, bo);
        #pragma unroll
        for (int i = 0; i < 8; i++) CPA(sb + asw0 + i * 2048u, agp0 + ao + i * astep);
        #pragma unroll
        for (int i = 0; i < 8; i++) CPA(sb + 16384u + asw0 + i * 2048u, bgp0 + bo + i * bstep);
        CP_COMMIT();
        if (1 < nIt) {
            offs(1, ao, bo);
            #pragma unroll
            for (int i = 0; i < 8; i++) CPA(sb + 32768u + asw0 + i * 2048u, agp0 + ao + i * astep);
            #pragma unroll
            for (int i = 0; i < 8; i++) CPA(sb + 49152u + asw0 + i * 2048u, bgp0 + bo + i * bstep);
        }
        CP_COMMIT();
    }

    int cur = 0;
    #pragma unroll 1
    for (int it = 0; it < nIt; ++it) {
        CP_WAIT1();
        __syncthreads();

        const uint32_t st = sb + (uint32_t)cur * 32768u;

        // preload ks=0 fragments (B all 8 nj, A for mi=0)
        uint32_t bf[2][8][2];
        uint32_t af[2][4];
        LDSM4(bf[0][0][0], bf[0][0][1], bf[0][1][0], bf[0][1][1], st + bbase[0]);
        LDSM4(bf[0][2][0], bf[0][2][1], bf[0][3][0], bf[0][3][1], st + bbase[1]);
        LDSM4(bf[0][4][0], bf[0][4][1], bf[0][5][0], bf[0][5][1], st + bbase[2]);
        LDSM4(bf[0][6][0], bf[0][6][1], bf[0][7][0], bf[0][7][1], st + bbase[3]);
        LDSM4(af[0][0], af[0][1], af[0][2], af[0][3], st + abase[0]);

        // issue next-next stage loads (latency overlapped with LDSM above)
        if (it + 2 < nIt) {
            long ao, bo;
            offs(it + 2, ao, bo);
            int nst = cur + 2; if (nst >= 3) nst -= 3;
            uint32_t stg = (uint32_t)nst * 32768u;
            #pragma unroll
            for (int i = 0; i < 8; i++) CPA(sb + stg + asw0 + i * 2048u, agp0 + ao + i * astep);
            #pragma unroll
            for (int i = 0; i < 8; i++) CPA(sb + stg + 16384u + asw0 + i * 2048u, bgp0 + bo + i * bstep);
        }
        CP_COMMIT();

        #pragma unroll
        for (int ks = 0; ks < 4; ks++) {
            const int cb = ks & 1;
            #pragma unroll
            for (int mi = 0; mi < 4; mi++) {
                // prefetch next fragments while MMAs below execute
                if (mi < 3) {
                    const uint32_t kx = (uint32_t)(ks << 5);
                    LDSM4(af[(mi + 1) & 1][0], af[(mi + 1) & 1][1],
                          af[(mi + 1) & 1][2], af[(mi + 1) & 1][3],
                          st + (abase[mi + 1] ^ kx));
                } else if (ks < 3) {
                    const int nb = cb ^ 1;
                    const uint32_t kxn = (uint32_t)((ks + 1) << 5);
                    LDSM4(bf[nb][0][0], bf[nb][0][1], bf[nb][1][0], bf[nb][1][1], st + (bbase[0] ^ kxn));
                    LDSM4(bf[nb][2][0], bf[nb][2][1], bf[nb][3][0], bf[nb][3][1], st + (bbase[1] ^ kxn));
                    LDSM4(bf[nb][4][0], bf[nb][4][1], bf[nb][5][0], bf[nb][5][1], st + (bbase[2] ^ kxn));
                    LDSM4(bf[nb][6][0], bf[nb][6][1], bf[nb][7][0], bf[nb][7][1], st + (bbase[3] ^ kxn));
                    LDSM4(af[0][0], af[0][1], af[0][2], af[0][3], st + (abase[0] ^ kxn));
                }
                const int ca = mi & 1;
                #pragma unroll
                for (int nj = 0; nj < 8; nj++)
                    MMA16816(acc[mi][nj], af[ca][0], af[ca][1], af[ca][2], af[ca][3],
                             bf[cb][nj][0], bf[cb][nj][1]);
            }
        }
        if (++cur == 3) cur = 0;
    }

    // ---------------- epilogue ----------------
    float* Cf = (float*)Cv + (long)blockIdx.z * sC;
    __nv_bfloat16* Cb = (__nv_bfloat16*)Cv + (long)blockIdx.z * sC;

    #pragma unroll
    for (int mi = 0; mi < 4; mi++) {
        const int m0 = bm + wm * 64 + mi * 16 + (lane >> 2);
        const int m1 = m0 + 8;
        const float bm0 = BIASM ? __ldg(&bias[m0]) : 0.f;
        const float bm1 = BIASM ? __ldg(&bias[m1]) : 0.f;
        float sc0 = 1.f, sc1 = 1.f;
        if (SCALEM) {
            sc0 = __ldg(&scalev[(long)blockIdx.z * LQ + m0]);
            sc1 = __ldg(&scalev[(long)blockIdx.z * LQ + m1]);
        }
        float s0 = 0.f, s1 = 0.f, q0 = 0.f, q1 = 0.f;
        #pragma unroll
        for (int nj = 0; nj < 8; nj++) {
            const int n = bn + wn * 64 + nj * 8 + (lane & 3) * 2;
            const float bn0 = BIASN ? __ldg(&bias[n])     : 0.f;
            const float bn1 = BIASN ? __ldg(&bias[n + 1]) : 0.f;
            float v00 = acc[mi][nj][0] + bm0 + bn0;
            float v01 = acc[mi][nj][1] + bm0 + bn1;
            float v10 = acc[mi][nj][2] + bm1 + bn0;
            float v11 = acc[mi][nj][3] + bm1 + bn1;
            if (SOFTEXP) {
                v00 = __expf(v00); v01 = __expf(v01);
                v10 = __expf(v10); v11 = __expf(v11);
                s0 += v00 + v01;
                s1 += v10 + v11;
            }
            if (BNSTAT) {
                s0 += v00 + v01; s1 += v10 + v11;
                q0 += v00 * v00 + v01 * v01;
                q1 += v10 * v10 + v11 * v11;
            }
            if (SCALEM) { v00 *= sc0; v01 *= sc0; v10 *= sc1; v11 *= sc1; }
            if (POOLM) {
                float p00 = fmaxf(v00, __shfl_xor_sync(~0u, v00, 4));
                float p01 = fmaxf(v01, __shfl_xor_sync(~0u, v01, 4));
                float p10 = fmaxf(v10, __shfl_xor_sync(~0u, v10, 4));
                float p11 = fmaxf(v11, __shfl_xor_sync(~0u, v11, 4));
                if (!(lane & 4)) {
                    int pr0 = m0 >> 1, pr1 = m1 >> 1;
                    __nv_bfloat16 h0 = __float2bfloat16(p00), h1 = __float2bfloat16(p01);
                    __nv_bfloat16 h2 = __float2bfloat16(p10), h3 = __float2bfloat16(p11);
                    __nv_bfloat162 hh0; hh0.x = h0; hh0.y = h1;
                    __nv_bfloat162 hh1; hh1.x = h2; hh1.y = h3;
                    __nv_bfloat162 ll0;
                    ll0.x = __float2bfloat16(p00 - __bfloat162float(h0));
                    ll0.y = __float2bfloat16(p01 - __bfloat162float(h1));
                    __nv_bfloat162 ll1;
                    ll1.x = __float2bfloat16(p10 - __bfloat162float(h2));
                    ll1.y = __float2bfloat16(p11 - __bfloat162float(h3));
                    *(__nv_bfloat162*)&Cb[(long)pr0 * ldc + n] = hh0;
                    *(__nv_bfloat162*)&Cb[(long)pr0 * ldc + lo_off + n] = ll0;
                    *(__nv_bfloat162*)&Cb[(long)pr1 * ldc + n] = hh1;
                    *(__nv_bfloat162*)&Cb[(long)pr1 * ldc + lo_off + n] = ll1;
                }
            } else if (POOLN) {
                float p0 = fmaxf(v00, v01);
                float p1 = fmaxf(v10, v11);
                int np = n >> 1;
                __nv_bfloat16 h0 = __float2bfloat16(p0);
                __nv_bfloat16 h1 = __float2bfloat16(p1);
                Cb[(long)m0 * ldc + np] = h0;
                Cb[(long)m0 * ldc + lo_off + np] = __float2bfloat16(p0 - __bfloat162float(h0));
                Cb[(long)m1 * ldc + np] = h1;
                Cb[(long)m1 * ldc + lo_off + np] = __float2bfloat16(p1 - __bfloat162float(h1));
            } else if (SPLIT || SOFTEXP) {
                __nv_bfloat16 h00 = __float2bfloat16(v00), h01 = __float2bfloat16(v01);
                __nv_bfloat16 h10 = __float2bfloat16(v10), h11 = __float2bfloat16(v11);
                __nv_bfloat162 hh0; hh0.x = h00; hh0.y = h01;
                __nv_bfloat162 hh1; hh1.x = h10; hh1.y = h11;
                __nv_bfloat162 ll0;
                ll0.x = __float2bfloat16(v00 - __bfloat162float(h00));
                ll0.y = __float2bfloat16(v01 - __bfloat162float(h01));
                __nv_bfloat162 ll1;
                ll1.x = __float2bfloat16(v10 - __bfloat162float(h10));
                ll1.y = __float2bfloat16(v11 - __bfloat162float(h11));
                *(__nv_bfloat162*)&Cb[(long)m0 * ldc + n] = hh0;
                *(__nv_bfloat162*)&Cb[(long)m0 * ldc + lo_off + n] = ll0;
                *(__nv_bfloat162*)&Cb[(long)m1 * ldc + n] = hh1;
                *(__nv_bfloat162*)&Cb[(long)m1 * ldc + lo_off + n] = ll1;
            } else {
                *(float2*)&Cf[(long)m0 * ldc + n] = make_float2(v00, v01);
                *(float2*)&Cf[(long)m1 * ldc + n] = make_float2(v10, v11);
            }
        }
        if (SOFTEXP) {
            s0 += __shfl_xor_sync(~0u, s0, 1);
            s0 += __shfl_xor_sync(~0u, s0, 2);
            s1 += __shfl_xor_sync(~0u, s1, 1);
            s1 += __shfl_xor_sync(~0u, s1, 2);
            if ((lane & 3) == 0) {
                long base = ((long)blockIdx.z * LQ + m0) * 32 + blockIdx.x * 2 + wn;
                psum[base] = s0;
                psum[base + 8 * 32] = s1;
            }
        }
        if (BNSTAT) {
            s0 += __shfl_xor_sync(~0u, s0, 1);
            s0 += __shfl_xor_sync(~0u, s0, 2);
            s1 += __shfl_xor_sync(~0u, s1, 1);
            s1 += __shfl_xor_sync(~0u, s1, 2);
            q0 += __shfl_xor_sync(~0u, q0, 1);
            q0 += __shfl_xor_sync(~0u, q0, 2);
            q1 += __shfl_xor_sync(~0u, q1, 1);
            q1 += __shfl_xor_sync(~0u, q1, 2);
            if ((lane & 3) == 0) {
                int col = blockIdx.z * 64 + blockIdx.x * 2 + wn;
                psum [(long)m0 * 512 + col] = s0;
                psum [(long)m1 * 512 + col] = s1;
                psumq[(long)m0 * 512 + col] = q0;
                psumq[(long)m1 * 512 + col] = q1;
            }
        }
    }
}

// --------------------------------------------------------------- aux kernels
__device__ __forceinline__ void split_store(__nv_bfloat16* hi_p, __nv_bfloat16* lo_p, float v) {
    __nv_bfloat16 h = __float2bfloat16(v);
    *hi_p = h;
    *lo_p = __float2bfloat16(v - __bfloat162float(h));
}

__global__ __launch_bounds__(256)
void wsplit_all_kernel(const float* __restrict__ tw, const float* __restrict__ pw,
                       const float* __restrict__ gw, const float* __restrict__ zw,
                       __nv_bfloat16* __restrict__ ot, __nv_bfloat16* __restrict__ op,
                       __nv_bfloat16* __restrict__ og, __nv_bfloat16* __restrict__ oz)
{
    int i = blockIdx.x * 256 + threadIdx.x;
    int which = i >> 17;
    int j = i & 131071;
    const float* w; __nv_bfloat16* o; int Kc;
    if      (which == 0) { w = tw; o = ot; Kc = 512; }
    else if (which == 1) { w = pw; o = op; Kc = 512; }
    else if (which == 2) { w = gw; o = og; Kc = 512; }
    else                 { w = zw; o = oz; Kc = 256; }
    int r = j / Kc, k = j - r * Kc;
    split_store(&o[(long)r * 2 * Kc + k], &o[(long)r * 2 * Kc + Kc + k], w[j]);
}

__global__ __launch_bounds__(256)
void transpose_split_kernel(const float* __restrict__ x, __nv_bfloat16* __restrict__ xt)
{
    __shared__ float t[32][33];
    int b = blockIdx.z;
    int l0 = blockIdx.x * 32, c0 = blockIdx.y * 32;
    int tx = threadIdx.x & 31, ty = threadIdx.x >> 5;
    const float* px = x + ((long)b * CFULL + c0) * LQ + l0;
    #pragma unroll
    for (int i = 0; i < 32; i += 8) t[ty + i][tx] = px[(long)(ty + i) * LQ + tx];
    __syncthreads();
    __nv_bfloat16* po = xt + ((long)b * LQ + l0) * 1024 + c0;
    #pragma unroll
    for (int i = 0; i < 32; i += 8) {
        float v = t[tx][ty + i];
        split_store(&po[(long)(ty + i) * 1024 + tx],
                    &po[(long)(ty + i) * 1024 + 512 + tx], v);
    }
}

__global__ __launch_bounds__(256)
void rowsum_inv_kernel(const float* __restrict__ psum, float* __restrict__ inv)
{
    int row = blockIdx.x * 8 + (threadIdx.x >> 5);
    int lane = threadIdx.x & 31;
    float s = psum[(long)row * 32 + lane];
    #pragma unroll
    for (int o = 16; o; o >>= 1) s += __shfl_xor_sync(~0u, s, o);
    if (lane == 0) inv[row] = 1.f / s;
}

__global__ __launch_bounds__(256)
void bn_reduce_kernel(const float* __restrict__ bns, const float* __restrict__ bnq,
                      float* __restrict__ mean, float* __restrict__ var)
{
    __shared__ float ss_s[8], ss_q[8];
    int c = blockIdx.x, tid = threadIdx.x, lane = tid & 31, warp = tid >> 5;
    float s = 0.f, q = 0.f;
    #pragma unroll
    for (int i = 0; i < 2; i++) {
        s += bns[(long)c * 512 + tid + i * 256];
        q += bnq[(long)c * 512 + tid + i * 256];
    }
    #pragma unroll
    for (int o = 16; o; o >>= 1) {
        s += __shfl_xor_sync(~0u, s, o);
        q += __shfl_xor_sync(~0u, q, o);
    }
    if (lane == 0) { ss_s[warp] = s; ss_q[warp] = q; }
    __syncthreads();
    if (tid == 0) {
        float S = 0.f, Q = 0.f;
        #pragma unroll
        for (int w = 0; w < 8; w++) { S += ss_s[w]; Q += ss_q[w]; }
        const float invN = 1.f / (float)(BATCH * LQ);
        float mu = S * invN;
        mean[c] = mu;
        var[c] = Q * invN - mu * mu;
    }
}

__global__ __launch_bounds__(256)
void bn_apply_kernel(const float* __restrict__ z, const float* __restrict__ x,
                     const float* __restrict__ gamma, const float* __restrict__ beta,
                     const float* __restrict__ mean, const float* __restrict__ var,
                     float* __restrict__ out)
{
    long base = ((long)blockIdx.x * 256 + threadIdx.x) * 4;
    int c = (int)((base >> 12) & (CFULL - 1));
    float scale = gamma[c] * rsqrtf(var[c] + 1e-5f);
    float shift = beta[c] - mean[c] * scale;
    float4 zv = *(const float4*)&z[base];
    float4 xv = *(const float4*)&x[base];
    float4 o;
    o.x = zv.x * scale + shift + xv.x;
    o.y = zv.y * scale + shift + xv.y;
    o.z = zv.z * scale + shift + xv.z;
    o.w = zv.w * scale + shift + xv.w;
    *(float4*)&out[base] = o;
}

// --------------------------------------------------------------- launch
extern "C" void kernel_launch(void* const* d_in, const int* in_sizes, int n_in,
                              void* d_out, int out_size)
{
    const float* x       = (const float*)d_in[0];
    const float* theta_w = (const float*)d_in[1];
    const float* theta_b = (const float*)d_in[2];
    const float* phi_w   = (const float*)d_in[3];
    const float* phi_b   = (const float*)d_in[4];
    const float* g_w     = (const float*)d_in[5];
    const float* g_b     = (const float*)d_in[6];
    const float* wz_w    = (const float*)d_in[7];
    const float* wz_b    = (const float*)d_in[8];
    const float* gamma   = (const float*)d_in[9];
    const float* beta    = (const float*)d_in[10];
    float* out = (float*)d_out;

    __nv_bfloat16 *xt, *thetaT, *phiPT, *gP, *fs, *yT, *wth, *wph, *wg, *wwz;
    float *psum, *inv, *z, *bns, *bnq, *mean, *var;
    cudaGetSymbolAddress((void**)&xt,     g_xt);
    cudaGetSymbolAddress((void**)&thetaT, g_thetaT);
    cudaGetSymbolAddress((void**)&phiPT,  g_phiPT);
    cudaGetSymbolAddress((void**)&gP,     g_gP);
    cudaGetSymbolAddress((void**)&fs,     g_fs);
    cudaGetSymbolAddress((void**)&psum,   g_psum);
    cudaGetSymbolAddress((void**)&inv,    g_inv);
    cudaGetSymbolAddress((void**)&yT,     g_yT);
    cudaGetSymbolAddress((void**)&z,      g_z);
    cudaGetSymbolAddress((void**)&bns,    g_bns);
    cudaGetSymbolAddress((void**)&bnq,    g_bnq);
    cudaGetSymbolAddress((void**)&wth,    g_wth);
    cudaGetSymbolAddress((void**)&wph,    g_wph);
    cudaGetSymbolAddress((void**)&wg,     g_wg);
    cudaGetSymbolAddress((void**)&wwz,    g_wwz);
    cudaGetSymbolAddress((void**)&mean,   g_mean);
    cudaGetSymbolAddress((void**)&var,    g_var);

    cudaFuncSetAttribute((const void*)mma_gemm<0,1,1,0,0,0,0,0>, cudaFuncAttributeMaxDynamicSharedMemorySize, SM_BYTES);
    cudaFuncSetAttribute((const void*)mma_gemm<0,1,1,1,0,0,0,0>, cudaFuncAttributeMaxDynamicSharedMemorySize, SM_BYTES);
    cudaFuncSetAttribute((const void*)mma_gemm<1,0,1,0,1,0,0,0>, cudaFuncAttributeMaxDynamicSharedMemorySize, SM_BYTES);
    cudaFuncSetAttribute((const void*)mma_gemm<0,0,0,0,0,1,0,0>, cudaFuncAttributeMaxDynamicSharedMemorySize, SM_BYTES);
    cudaFuncSetAttribute((const void*)mma_gemm<0,0,1,0,0,0,1,0>, cudaFuncAttributeMaxDynamicSharedMemorySize, SM_BYTES);
    cudaFuncSetAttribute((const void*)mma_gemm<1,0,0,0,0,0,0,1>, cudaFuncAttributeMaxDynamicSharedMemorySize, SM_BYTES);

    dim3 blk(256);
    dim3 mblk(128);

    wsplit_all_kernel<<<2048, blk>>>(theta_w, phi_w, g_w, wz_w, wth, wph, wg, wwz);
    transpose_split_kernel<<<dim3(LQ / 32, CFULL / 32, BATCH), blk>>>(x, xt);

    // thetaT[L,Ci] split = xT * theta_w^T  (+bias n)
    mma_gemm<0,1,1,0,0,0,0,0><<<dim3(2, 32, BATCH), mblk, SM_BYTES>>>(
        xt, wth, theta_b, nullptr, nullptr, nullptr, thetaT, 512, 1024, 1024, 512, 256,
        (long)LQ * 1024, 0L, (long)LQ * 512);

    // phiP[L/2,Ci] split = maxpool_m(xT * phi_w^T + bias n)
    mma_gemm<0,1,1,1,0,0,0,0><<<dim3(2, 32, BATCH), mblk, SM_BYTES>>>(
        xt, wph, phi_b, nullptr, nullptr, nullptr, phiPT, 512, 1024, 1024, 512, 256,
        (long)LQ * 1024, 0L, (long)LK * 512);

    // gP[Ci,L/2] split = maxpool_n(g_w * xT^T + bias m)
    mma_gemm<1,0,1,0,1,0,0,0><<<dim3(32, 2, BATCH), mblk, SM_BYTES>>>(
        wg, xt, g_b, nullptr, nullptr, nullptr, gP, 512, 1024, 1024, 4096, 2048,
        0L, (long)LQ * 1024, (long)CI * 4096);

    // fs = exp(thetaT * phiP^T) split bf16, plus partial row sums
    mma_gemm<0,0,0,0,0,1,0,0><<<dim3(16, 32, BATCH), mblk, SM_BYTES>>>(
        thetaT, phiPT, nullptr, nullptr, psum, nullptr, fs, 256, 512, 512, 4096, 2048,
        (long)LQ * 512, (long)LK * 512, (long)LQ * 4096);

    rowsum_inv_kernel<<<BATCH * LQ / 8, blk>>>(psum, inv);

    // yT[L,Ci] split = (fs_split * gP_split^T) * inv[row]  (3 terms)
    mma_gemm<0,0,1,0,0,0,1,0><<<dim3(2, 32, BATCH), mblk, SM_BYTES>>>(
        fs, gP, nullptr, inv, nullptr, nullptr, yT, 2048, 4096, 4096, 512, 256,
        (long)LQ * 4096, (long)CI * 4096, (long)LQ * 512);

    // z[C,L] fp32 = wz_w * yT^T  (+bias m), with fused BN partial stats
    mma_gemm<1,0,0,0,0,0,0,1><<<dim3(32, 4, BATCH), mblk, SM_BYTES>>>(
        wwz, yT, wz_b, nullptr, bns, bnq, z, 256, 512, 512, LQ, 0,
        0L, (long)LQ * 512, (long)CFULL * LQ);

    bn_reduce_kernel<<<CFULL, blk>>>(bns, bnq, mean, var);
    bn_apply_kernel<<<(BATCH * CFULL * LQ) / (256 * 4), blk>>>(
        z, x, gamma, beta, mean, var, out);
}